// round 6
// baseline (speedup 1.0000x reference)
#include <cuda_runtime.h>

// Problem shape (fixed per reference): B=4, S=2048, D=1024, fp32.
#define BATCH 4
#define SEQ   2048
#define DIM   1024

// Scratch (device globals: allocation-guard safe).
__device__ float g_q[(size_t)BATCH * SEQ * DIM];              // 32 MB
__device__ float g_k[(size_t)BATCH * SEQ * DIM];              // 32 MB
__device__ float g_v[(size_t)BATCH * SEQ * DIM];              // 32 MB
__device__ float g_s[(size_t)BATCH * SEQ * SEQ];              // 64 MB (scores / probs)

// ---------------------------------------------------------------------------
// SGEMM: C = A @ B (+bias), fp32, 128x128x16 tile, 8x8 microtile, 256 threads,
// double-buffered smem, ldg->reg prefetch. All dims must divide tile sizes
// (true for every GEMM here), so no bounds checks.
//   TRANSB=false: B row-major [K, N]   (projections, P@V)
//   TRANSB=true : B row-major [N, K], C = A @ B^T  (Q@K^T)
// blockIdx.z selects batch via strides sA/sB/sC.
// ---------------------------------------------------------------------------
constexpr int BM = 128, BN = 128, BK = 16, TM = 8, TN = 8, PAD = 4;

template<bool TRANSB, bool BIAS>
__global__ __launch_bounds__(256, 2)
void sgemm_kernel(const float* __restrict__ A, const float* __restrict__ B,
                  const float* __restrict__ bias, float* __restrict__ C,
                  int M, int N, int K,
                  size_t sA, size_t sB, size_t sC)
{
    A += (size_t)blockIdx.z * sA;
    B += (size_t)blockIdx.z * sB;
    C += (size_t)blockIdx.z * sC;

    const int brow = blockIdx.y * BM;
    const int bcol = blockIdx.x * BN;
    const int tid  = threadIdx.x;

    __shared__ float As[2][BK][BM + PAD];
    __shared__ float Bs[2][BK][BN + PAD];

    const int tx   = tid & 15;
    const int ty   = tid >> 4;
    const int row0 = ty * TM;
    const int col0 = tx * TN;

    // A-tile (and NT B-tile) loader mapping: 128 rows x 16 cols, float4
    const int aR = tid >> 2;            // 0..63 (second load at +64)
    const int aC = (tid & 3) * 4;       // 0,4,8,12
    // NN B-tile loader mapping: 16 rows x 128 cols, float4
    const int bR = tid >> 5;            // 0..7 (second load at +8)
    const int bC = (tid & 31) * 4;

    float acc[TM][TN];
    #pragma unroll
    for (int i = 0; i < TM; i++)
        #pragma unroll
        for (int j = 0; j < TN; j++) acc[i][j] = 0.f;

    const float* Aptr = A + (size_t)(brow + aR) * K + aC;

    float4 ra0, ra1, rb0, rb1;

    // ---- prologue: fetch + store tile 0 ----
    ra0 = *(const float4*)(Aptr);
    ra1 = *(const float4*)(Aptr + (size_t)64 * K);
    if (TRANSB) {
        const float* Bp = B + (size_t)(bcol + aR) * K + aC;
        rb0 = *(const float4*)(Bp);
        rb1 = *(const float4*)(Bp + (size_t)64 * K);
    } else {
        const float* Bp = B + (size_t)bR * N + bcol + bC;
        rb0 = *(const float4*)(Bp);
        rb1 = *(const float4*)(Bp + (size_t)8 * N);
    }
    {
        As[0][aC + 0][aR] = ra0.x; As[0][aC + 1][aR] = ra0.y;
        As[0][aC + 2][aR] = ra0.z; As[0][aC + 3][aR] = ra0.w;
        As[0][aC + 0][aR + 64] = ra1.x; As[0][aC + 1][aR + 64] = ra1.y;
        As[0][aC + 2][aR + 64] = ra1.z; As[0][aC + 3][aR + 64] = ra1.w;
        if (TRANSB) {
            Bs[0][aC + 0][aR] = rb0.x; Bs[0][aC + 1][aR] = rb0.y;
            Bs[0][aC + 2][aR] = rb0.z; Bs[0][aC + 3][aR] = rb0.w;
            Bs[0][aC + 0][aR + 64] = rb1.x; Bs[0][aC + 1][aR + 64] = rb1.y;
            Bs[0][aC + 2][aR + 64] = rb1.z; Bs[0][aC + 3][aR + 64] = rb1.w;
        } else {
            *(float4*)&Bs[0][bR][bC]     = rb0;
            *(float4*)&Bs[0][bR + 8][bC] = rb1;
        }
    }
    __syncthreads();

    const int nt = K / BK;
    for (int t = 0; t < nt; t++) {
        const int cur = t & 1;
        const int nxt = cur ^ 1;

        if (t + 1 < nt) {                       // prefetch next tile into regs
            const int k0 = (t + 1) * BK;
            ra0 = *(const float4*)(Aptr + k0);
            ra1 = *(const float4*)(Aptr + k0 + (size_t)64 * K);
            if (TRANSB) {
                const float* Bp = B + (size_t)(bcol + aR) * K + k0 + aC;
                rb0 = *(const float4*)(Bp);
                rb1 = *(const float4*)(Bp + (size_t)64 * K);
            } else {
                const float* Bp = B + (size_t)(k0 + bR) * N + bcol + bC;
                rb0 = *(const float4*)(Bp);
                rb1 = *(const float4*)(Bp + (size_t)8 * N);
            }
        }

        #pragma unroll
        for (int kk = 0; kk < BK; kk++) {
            float a[TM], b[TN];
            *(float4*)&a[0] = *(const float4*)&As[cur][kk][row0];
            *(float4*)&a[4] = *(const float4*)&As[cur][kk][row0 + 4];
            *(float4*)&b[0] = *(const float4*)&Bs[cur][kk][col0];
            *(float4*)&b[4] = *(const float4*)&Bs[cur][kk][col0 + 4];
            #pragma unroll
            for (int i = 0; i < TM; i++)
                #pragma unroll
                for (int j = 0; j < TN; j++)
                    acc[i][j] = fmaf(a[i], b[j], acc[i][j]);
        }

        if (t + 1 < nt) {                       // store prefetched tile
            As[nxt][aC + 0][aR] = ra0.x; As[nxt][aC + 1][aR] = ra0.y;
            As[nxt][aC + 2][aR] = ra0.z; As[nxt][aC + 3][aR] = ra0.w;
            As[nxt][aC + 0][aR + 64] = ra1.x; As[nxt][aC + 1][aR + 64] = ra1.y;
            As[nxt][aC + 2][aR + 64] = ra1.z; As[nxt][aC + 3][aR + 64] = ra1.w;
            if (TRANSB) {
                Bs[nxt][aC + 0][aR] = rb0.x; Bs[nxt][aC + 1][aR] = rb0.y;
                Bs[nxt][aC + 2][aR] = rb0.z; Bs[nxt][aC + 3][aR] = rb0.w;
                Bs[nxt][aC + 0][aR + 64] = rb1.x; Bs[nxt][aC + 1][aR + 64] = rb1.y;
                Bs[nxt][aC + 2][aR + 64] = rb1.z; Bs[nxt][aC + 3][aR + 64] = rb1.w;
            } else {
                *(float4*)&Bs[nxt][bR][bC]     = rb0;
                *(float4*)&Bs[nxt][bR + 8][bC] = rb1;
            }
        }
        __syncthreads();
    }

    float bf[TN];
    #pragma unroll
    for (int j = 0; j < TN; j++) bf[j] = BIAS ? bias[bcol + col0 + j] : 0.f;

    #pragma unroll
    for (int i = 0; i < TM; i++) {
        float* Cp = C + (size_t)(brow + row0 + i) * N + bcol + col0;
        float4 o0 = make_float4(acc[i][0] + bf[0], acc[i][1] + bf[1],
                                acc[i][2] + bf[2], acc[i][3] + bf[3]);
        float4 o1 = make_float4(acc[i][4] + bf[4], acc[i][5] + bf[5],
                                acc[i][6] + bf[6], acc[i][7] + bf[7]);
        *(float4*)(Cp)     = o0;
        *(float4*)(Cp + 4) = o1;
    }
}

// ---------------------------------------------------------------------------
// Row softmax, row length 2048, one block (256 thr) per row, in-place.
// ---------------------------------------------------------------------------
__global__ __launch_bounds__(256)
void softmax2048_kernel(float* __restrict__ S)
{
    const int tid = threadIdx.x;
    float4* row = reinterpret_cast<float4*>(S + (size_t)blockIdx.x * 2048);
    float4 v0 = row[tid];
    float4 v1 = row[tid + 256];

    __shared__ float smax[8];
    __shared__ float ssum[8];

    float m = fmaxf(fmaxf(fmaxf(v0.x, v0.y), fmaxf(v0.z, v0.w)),
                    fmaxf(fmaxf(v1.x, v1.y), fmaxf(v1.z, v1.w)));
    #pragma unroll
    for (int o = 16; o; o >>= 1) m = fmaxf(m, __shfl_xor_sync(0xffffffffu, m, o));
    if ((tid & 31) == 0) smax[tid >> 5] = m;
    __syncthreads();
    m = smax[0];
    #pragma unroll
    for (int i = 1; i < 8; i++) m = fmaxf(m, smax[i]);

    v0.x = __expf(v0.x - m); v0.y = __expf(v0.y - m);
    v0.z = __expf(v0.z - m); v0.w = __expf(v0.w - m);
    v1.x = __expf(v1.x - m); v1.y = __expf(v1.y - m);
    v1.z = __expf(v1.z - m); v1.w = __expf(v1.w - m);

    float s = v0.x + v0.y + v0.z + v0.w + v1.x + v1.y + v1.z + v1.w;
    #pragma unroll
    for (int o = 16; o; o >>= 1) s += __shfl_xor_sync(0xffffffffu, s, o);
    if ((tid & 31) == 0) ssum[tid >> 5] = s;
    __syncthreads();
    s = 0.f;
    #pragma unroll
    for (int i = 0; i < 8; i++) s += ssum[i];

    const float inv = 1.0f / s;
    v0.x *= inv; v0.y *= inv; v0.z *= inv; v0.w *= inv;
    v1.x *= inv; v1.y *= inv; v1.z *= inv; v1.w *= inv;
    row[tid]       = v0;
    row[tid + 256] = v1;
}

// ---------------------------------------------------------------------------
// Launch: 3 projection GEMMs -> scores (NT, batched) -> softmax -> PV (NN).
// Inputs (metadata order): x, Wq, bq, Wk, bk, Wv, bv.  Output: [B,S,D] fp32.
// ---------------------------------------------------------------------------
extern "C" void kernel_launch(void* const* d_in, const int* in_sizes, int n_in,
                              void* d_out, int out_size)
{
    const float* x  = (const float*)d_in[0];
    const float* Wq = (const float*)d_in[1];
    const float* bq = (const float*)d_in[2];
    const float* Wk = (const float*)d_in[3];
    const float* bk = (const float*)d_in[4];
    const float* Wv = (const float*)d_in[5];
    const float* bv = (const float*)d_in[6];
    float* out = (float*)d_out;

    float *q, *k, *v, *s;
    cudaGetSymbolAddress((void**)&q, g_q);
    cudaGetSymbolAddress((void**)&k, g_k);
    cudaGetSymbolAddress((void**)&v, g_v);
    cudaGetSymbolAddress((void**)&s, g_s);

    const dim3 blk(256);

    // QKV projections: [8192,1024] @ [1024,1024] + bias
    const dim3 gp(DIM / BN, (BATCH * SEQ) / BM);          // (8, 64)
    sgemm_kernel<false, true><<<gp, blk>>>(x, Wq, bq, q,
        BATCH * SEQ, DIM, DIM, 0, 0, 0);
    sgemm_kernel<false, true><<<gp, blk>>>(x, Wk, bk, k,
        BATCH * SEQ, DIM, DIM, 0, 0, 0);
    sgemm_kernel<false, true><<<gp, blk>>>(x, Wv, bv, v,
        BATCH * SEQ, DIM, DIM, 0, 0, 0);

    // scores = Q @ K^T per batch: [2048,1024] @ [2048,1024]^T
    const dim3 gs(SEQ / BN, SEQ / BM, BATCH);             // (16, 16, 4)
    sgemm_kernel<true, false><<<gs, blk>>>(q, k, nullptr, s,
        SEQ, SEQ, DIM,
        (size_t)SEQ * DIM, (size_t)SEQ * DIM, (size_t)SEQ * SEQ);

    // softmax over each of the B*S rows (length 2048), in place
    softmax2048_kernel<<<BATCH * SEQ, 256>>>(s);

    // out = P @ V per batch: [2048,2048] @ [2048,1024]
    const dim3 go(DIM / BN, SEQ / BM, BATCH);             // (8, 16, 4)
    sgemm_kernel<false, false><<<go, blk>>>(s, v, nullptr, out,
        SEQ, DIM, SEQ,
        (size_t)SEQ * SEQ, (size_t)SEQ * DIM, (size_t)SEQ * DIM);
}

// round 7
// speedup vs baseline: 1.3501x; 1.3501x over previous
#include <cuda_runtime.h>
#include <cuda_bf16.h>
#include <cstdint>

// Problem shape (fixed per reference): B=4, S=2048, D=1024, fp32.
#define BATCH 4
#define SEQ   2048
#define DIM   1024

// Scratch (device globals: allocation-guard safe).
__device__ float g_q[(size_t)BATCH * SEQ * DIM];              // 32 MB
__device__ float g_k[(size_t)BATCH * SEQ * DIM];              // 32 MB
__device__ float g_v[(size_t)BATCH * SEQ * DIM];              // 32 MB
__device__ float g_s[(size_t)BATCH * SEQ * SEQ];              // 64 MB (scores / probs)

// ---------------------------------------------------------------------------
// PTX helpers
// ---------------------------------------------------------------------------
__device__ __forceinline__ uint32_t smem_u32(const void* p) {
    return (uint32_t)__cvta_generic_to_shared(p);
}

__device__ __forceinline__ void ldsm_x4(uint32_t& r0, uint32_t& r1,
                                        uint32_t& r2, uint32_t& r3, uint32_t a) {
    asm volatile("ldmatrix.sync.aligned.m8n8.x4.shared.b16 {%0,%1,%2,%3},[%4];"
                 : "=r"(r0), "=r"(r1), "=r"(r2), "=r"(r3) : "r"(a));
}
__device__ __forceinline__ void ldsm_x2(uint32_t& r0, uint32_t& r1, uint32_t a) {
    asm volatile("ldmatrix.sync.aligned.m8n8.x2.shared.b16 {%0,%1},[%2];"
                 : "=r"(r0), "=r"(r1) : "r"(a));
}
__device__ __forceinline__ void ldsm_x2_t(uint32_t& r0, uint32_t& r1, uint32_t a) {
    asm volatile("ldmatrix.sync.aligned.m8n8.x2.trans.shared.b16 {%0,%1},[%2];"
                 : "=r"(r0), "=r"(r1) : "r"(a));
}
__device__ __forceinline__ void mma16816(float* c,
                                         uint32_t a0, uint32_t a1, uint32_t a2, uint32_t a3,
                                         uint32_t b0, uint32_t b1) {
    asm volatile(
        "mma.sync.aligned.m16n8k16.row.col.f32.bf16.bf16.f32 "
        "{%0,%1,%2,%3},{%4,%5,%6,%7},{%8,%9},{%0,%1,%2,%3};"
        : "+f"(c[0]), "+f"(c[1]), "+f"(c[2]), "+f"(c[3])
        : "r"(a0), "r"(a1), "r"(a2), "r"(a3), "r"(b0), "r"(b1));
}

// fp32 pair -> (hi, lo) bf16x2 packed words.  x = hi + lo + O(2^-17 |x|)
__device__ __forceinline__ void split_pack(float x, float y, uint32_t& hi, uint32_t& lo) {
    __nv_bfloat16 hx = __float2bfloat16(x);
    __nv_bfloat16 hy = __float2bfloat16(y);
    __nv_bfloat162 h2; h2.x = hx; h2.y = hy;
    __nv_bfloat162 l2;
    l2.x = __float2bfloat16(x - __bfloat162float(hx));
    l2.y = __float2bfloat16(y - __bfloat162float(hy));
    hi = *reinterpret_cast<uint32_t*>(&h2);
    lo = *reinterpret_cast<uint32_t*>(&l2);
}

// ---------------------------------------------------------------------------
// bf16-split tensor-core GEMM.  C = A @ B (+bias) in "fp32-like" precision:
//   A = Ah + Al, B = Bh + Bl (bf16);  acc += Ah*Bh + Ah*Bl + Al*Bh (fp32 acc).
// Block tile 128x128x32, 512 threads = 16 warps (4x4), warp tile 32x32.
// TRANSB=false: B row-major [K,N].  TRANSB=true: B row-major [N,K], C=A@B^T.
// All dims divide tile sizes; no predication.  blockIdx.z = batch.
// ---------------------------------------------------------------------------
constexpr int LDA   = 40;            // 32 + 8 pad (bf16 elems) -> conflict-free ldsm
constexpr int LDB_T = 40;
constexpr int LDB_N = 136;           // 128 + 8 pad
constexpr int A_T   = 128 * LDA;     // elems per A stage tile
constexpr int B_TT  = 128 * LDB_T;
constexpr int B_TN  = 32 * LDB_N;

constexpr size_t SMEM_T = (size_t)8 * (A_T + B_TT);  // bytes, TRANSB variant
constexpr size_t SMEM_N = (size_t)8 * (A_T + B_TN);  // bytes, NN variant

template<bool TRANSB>
__device__ __forceinline__ void load_tile(const float* __restrict__ A,
                                          const float* __restrict__ Bm,
                                          int K, int N, int brow, int bcol, int k0,
                                          int tid, float4 (&pa)[2], float4 (&pb)[2]) {
    const int rA = tid >> 2, cA = (tid & 3) * 8;
    const float* ap = A + (size_t)(brow + rA) * K + k0 + cA;
    pa[0] = *(const float4*)ap;
    pa[1] = *(const float4*)(ap + 4);
    if (TRANSB) {
        const float* bp = Bm + (size_t)(bcol + rA) * K + k0 + cA;
        pb[0] = *(const float4*)bp;
        pb[1] = *(const float4*)(bp + 4);
    } else {
        const int rB = tid >> 4, cB = (tid & 15) * 8;
        const float* bp = Bm + (size_t)(k0 + rB) * N + bcol + cB;
        pb[0] = *(const float4*)bp;
        pb[1] = *(const float4*)(bp + 4);
    }
}

template<bool TRANSB>
__device__ __forceinline__ void store_tile(__nv_bfloat16* sAh, __nv_bfloat16* sAl,
                                           __nv_bfloat16* sBh, __nv_bfloat16* sBl,
                                           int tid, const float4 (&pa)[2], const float4 (&pb)[2]) {
    const int rA = tid >> 2, cA = (tid & 3) * 8;
    #pragma unroll
    for (int i = 0; i < 2; i++) {
        uint32_t h0, l0, h1, l1;
        split_pack(pa[i].x, pa[i].y, h0, l0);
        split_pack(pa[i].z, pa[i].w, h1, l1);
        *(uint2*)&sAh[rA * LDA + cA + i * 4] = make_uint2(h0, h1);
        *(uint2*)&sAl[rA * LDA + cA + i * 4] = make_uint2(l0, l1);
    }
    if (TRANSB) {
        #pragma unroll
        for (int i = 0; i < 2; i++) {
            uint32_t h0, l0, h1, l1;
            split_pack(pb[i].x, pb[i].y, h0, l0);
            split_pack(pb[i].z, pb[i].w, h1, l1);
            *(uint2*)&sBh[rA * LDB_T + cA + i * 4] = make_uint2(h0, h1);
            *(uint2*)&sBl[rA * LDB_T + cA + i * 4] = make_uint2(l0, l1);
        }
    } else {
        const int rB = tid >> 4, cB = (tid & 15) * 8;
        #pragma unroll
        for (int i = 0; i < 2; i++) {
            uint32_t h0, l0, h1, l1;
            split_pack(pb[i].x, pb[i].y, h0, l0);
            split_pack(pb[i].z, pb[i].w, h1, l1);
            *(uint2*)&sBh[rB * LDB_N + cB + i * 4] = make_uint2(h0, h1);
            *(uint2*)&sBl[rB * LDB_N + cB + i * 4] = make_uint2(l0, l1);
        }
    }
}

template<bool TRANSB, bool BIAS>
__global__ __launch_bounds__(512)
void mma_gemm(const float* __restrict__ A, const float* __restrict__ Bm,
              const float* __restrict__ bias, float* __restrict__ C,
              int M, int N, int K, size_t sA, size_t sB, size_t sC)
{
    constexpr int LDB = TRANSB ? LDB_T : LDB_N;
    constexpr int B_T = TRANSB ? B_TT : B_TN;

    extern __shared__ __align__(16) __nv_bfloat16 sm[];
    __nv_bfloat16* sAh = sm;
    __nv_bfloat16* sAl = sAh + 2 * A_T;
    __nv_bfloat16* sBh = sAl + 2 * A_T;
    __nv_bfloat16* sBl = sBh + 2 * B_T;

    A  += (size_t)blockIdx.z * sA;
    Bm += (size_t)blockIdx.z * sB;
    C  += (size_t)blockIdx.z * sC;

    const int brow = blockIdx.y * 128;
    const int bcol = blockIdx.x * 128;
    const int tid  = threadIdx.x;
    const int lane = tid & 31;
    const int warp = tid >> 5;
    const int mw   = (warp & 3) * 32;   // warp m-offset in tile
    const int nw   = (warp >> 2) * 32;  // warp n-offset in tile

    float acc[2][4][4] = {};

    float4 pa[2], pb[2];
    load_tile<TRANSB>(A, Bm, K, N, brow, bcol, 0, tid, pa, pb);
    store_tile<TRANSB>(sAh, sAl, sBh, sBl, tid, pa, pb);
    __syncthreads();

    // lane-invariant fragment addressing pieces
    const int r8  = lane & 7;
    const int sel = lane >> 3;              // 0..3 (x4); (sel&1) used for x2
    const int aRow    = mw + r8 + (sel & 1) * 8;   // + i*16
    const int aColOff = (sel >> 1) * 8;            // + ks
    const int bSel    = sel & 1;

    const int nt = K / 32;
    for (int t = 0; t < nt; t++) {
        if (t + 1 < nt)
            load_tile<TRANSB>(A, Bm, K, N, brow, bcol, (t + 1) * 32, tid, pa, pb);

        const int st = t & 1;
        const uint32_t baseAh = smem_u32(sAh + st * A_T);
        const uint32_t baseAl = smem_u32(sAl + st * A_T);
        const uint32_t baseBh = smem_u32(sBh + st * B_T);
        const uint32_t baseBl = smem_u32(sBl + st * B_T);

        #pragma unroll
        for (int ks = 0; ks < 32; ks += 16) {
            uint32_t bh[4][2], bl[4][2];
            #pragma unroll
            for (int j = 0; j < 4; j++) {
                if (TRANSB) {
                    const int off = (nw + j * 8 + r8) * LDB + ks + bSel * 8;
                    ldsm_x2(bh[j][0], bh[j][1], baseBh + off * 2);
                    ldsm_x2(bl[j][0], bl[j][1], baseBl + off * 2);
                } else {
                    const int off = (ks + bSel * 8 + r8) * LDB + nw + j * 8;
                    ldsm_x2_t(bh[j][0], bh[j][1], baseBh + off * 2);
                    ldsm_x2_t(bl[j][0], bl[j][1], baseBl + off * 2);
                }
            }
            #pragma unroll
            for (int i = 0; i < 2; i++) {
                const int off = (aRow + i * 16) * LDA + ks + aColOff;
                uint32_t ah0, ah1, ah2, ah3, al0, al1, al2, al3;
                ldsm_x4(ah0, ah1, ah2, ah3, baseAh + off * 2);
                ldsm_x4(al0, al1, al2, al3, baseAl + off * 2);
                #pragma unroll
                for (int j = 0; j < 4; j++) {
                    mma16816(acc[i][j], ah0, ah1, ah2, ah3, bh[j][0], bh[j][1]);
                    mma16816(acc[i][j], ah0, ah1, ah2, ah3, bl[j][0], bl[j][1]);
                    mma16816(acc[i][j], al0, al1, al2, al3, bh[j][0], bh[j][1]);
                }
            }
        }

        if (t + 1 < nt) {
            const int nx = st ^ 1;
            store_tile<TRANSB>(sAh + nx * A_T, sAl + nx * A_T,
                               sBh + nx * B_T, sBl + nx * B_T, tid, pa, pb);
        }
        __syncthreads();
    }

    // epilogue: c-frag layout -> global fp32
    const int g  = lane >> 2;
    const int tg = lane & 3;
    #pragma unroll
    for (int i = 0; i < 2; i++) {
        #pragma unroll
        for (int j = 0; j < 4; j++) {
            const int m = brow + mw + i * 16 + g;
            const int n = bcol + nw + j * 8 + tg * 2;
            float b0 = 0.f, b1 = 0.f;
            if (BIAS) { b0 = bias[n]; b1 = bias[n + 1]; }
            *(float2*)&C[(size_t)m * N + n] =
                make_float2(acc[i][j][0] + b0, acc[i][j][1] + b1);
            *(float2*)&C[(size_t)(m + 8) * N + n] =
                make_float2(acc[i][j][2] + b0, acc[i][j][3] + b1);
        }
    }
}

// ---------------------------------------------------------------------------
// Row softmax, length 2048, ONE WARP per row (MLP=16 per lane), in-place.
// Block = 256 threads = 8 rows.
// ---------------------------------------------------------------------------
__global__ __launch_bounds__(256)
void softmax_warp(float* __restrict__ S)
{
    const int lane = threadIdx.x & 31;
    const int warp = threadIdx.x >> 5;
    const size_t row = (size_t)blockIdx.x * 8 + warp;
    float4* p = reinterpret_cast<float4*>(S + row * 2048);

    float4 v[16];
    #pragma unroll
    for (int i = 0; i < 16; i++) v[i] = p[lane + 32 * i];

    float m = -3.0e38f;
    #pragma unroll
    for (int i = 0; i < 16; i++)
        m = fmaxf(m, fmaxf(fmaxf(v[i].x, v[i].y), fmaxf(v[i].z, v[i].w)));
    #pragma unroll
    for (int o = 16; o; o >>= 1) m = fmaxf(m, __shfl_xor_sync(0xffffffffu, m, o));

    float s = 0.f;
    #pragma unroll
    for (int i = 0; i < 16; i++) {
        v[i].x = __expf(v[i].x - m); v[i].y = __expf(v[i].y - m);
        v[i].z = __expf(v[i].z - m); v[i].w = __expf(v[i].w - m);
        s += v[i].x + v[i].y + v[i].z + v[i].w;
    }
    #pragma unroll
    for (int o = 16; o; o >>= 1) s += __shfl_xor_sync(0xffffffffu, s, o);

    const float inv = 1.0f / s;
    #pragma unroll
    for (int i = 0; i < 16; i++) {
        v[i].x *= inv; v[i].y *= inv; v[i].z *= inv; v[i].w *= inv;
        p[lane + 32 * i] = v[i];
    }
}

// ---------------------------------------------------------------------------
// Launch: QKV projections -> scores (NT, batched) -> softmax -> PV (NN).
// Inputs (metadata order): x, Wq, bq, Wk, bk, Wv, bv.  Output: [B,S,D] fp32.
// ---------------------------------------------------------------------------
extern "C" void kernel_launch(void* const* d_in, const int* in_sizes, int n_in,
                              void* d_out, int out_size)
{
    const float* x  = (const float*)d_in[0];
    const float* Wq = (const float*)d_in[1];
    const float* bq = (const float*)d_in[2];
    const float* Wk = (const float*)d_in[3];
    const float* bk = (const float*)d_in[4];
    const float* Wv = (const float*)d_in[5];
    const float* bv = (const float*)d_in[6];
    float* out = (float*)d_out;

    float *q, *k, *v, *s;
    cudaGetSymbolAddress((void**)&q, g_q);
    cudaGetSymbolAddress((void**)&k, g_k);
    cudaGetSymbolAddress((void**)&v, g_v);
    cudaGetSymbolAddress((void**)&s, g_s);

    cudaFuncSetAttribute(mma_gemm<false, true>,
                         cudaFuncAttributeMaxDynamicSharedMemorySize, (int)SMEM_N);
    cudaFuncSetAttribute(mma_gemm<false, false>,
                         cudaFuncAttributeMaxDynamicSharedMemorySize, (int)SMEM_N);
    cudaFuncSetAttribute(mma_gemm<true, false>,
                         cudaFuncAttributeMaxDynamicSharedMemorySize, (int)SMEM_T);

    const dim3 blk(512);

    // QKV projections: [8192,1024] @ [1024,1024] + bias
    const dim3 gp(DIM / 128, (BATCH * SEQ) / 128);           // (8, 64)
    mma_gemm<false, true><<<gp, blk, SMEM_N>>>(x, Wq, bq, q,
        BATCH * SEQ, DIM, DIM, 0, 0, 0);
    mma_gemm<false, true><<<gp, blk, SMEM_N>>>(x, Wk, bk, k,
        BATCH * SEQ, DIM, DIM, 0, 0, 0);
    mma_gemm<false, true><<<gp, blk, SMEM_N>>>(x, Wv, bv, v,
        BATCH * SEQ, DIM, DIM, 0, 0, 0);

    // scores = Q @ K^T per batch: [2048,1024] @ [2048,1024]^T
    const dim3 gs(SEQ / 128, SEQ / 128, BATCH);              // (16, 16, 4)
    mma_gemm<true, false><<<gs, blk, SMEM_T>>>(q, k, nullptr, s,
        SEQ, SEQ, DIM,
        (size_t)SEQ * DIM, (size_t)SEQ * DIM, (size_t)SEQ * SEQ);

    // softmax over each of the B*S rows (length 2048), in place
    softmax_warp<<<(BATCH * SEQ) / 8, 256>>>(s);

    // out = P @ V per batch: [2048,2048] @ [2048,1024]
    const dim3 go(DIM / 128, SEQ / 128, BATCH);              // (8, 16, 4)
    mma_gemm<false, false><<<go, blk, SMEM_N>>>(s, v, nullptr, out,
        SEQ, DIM, SEQ,
        (size_t)SEQ * SEQ, (size_t)SEQ * DIM, (size_t)SEQ * DIM);
}

// round 10
// speedup vs baseline: 2.6475x; 1.9610x over previous
#include <cuda_runtime.h>
#include <cuda_bf16.h>
#include <cstdint>

// Problem shape (fixed per reference): B=4, S=2048, D=1024, fp32.
#define BATCH 4
#define SEQ   2048
#define DIM   1024
#define MTOT  (BATCH * SEQ)          // 8192

// ---------------------------------------------------------------------------
// Scratch (device globals: allocation-guard safe).
// ---------------------------------------------------------------------------
__device__ __nv_bfloat16 g_xh[(size_t)MTOT * DIM], g_xl[(size_t)MTOT * DIM];
__device__ __nv_bfloat16 g_wth[(size_t)3 * DIM * DIM], g_wtl[(size_t)3 * DIM * DIM];
__device__ __nv_bfloat16 g_qh[(size_t)MTOT * DIM],  g_ql[(size_t)MTOT * DIM];
__device__ __nv_bfloat16 g_kh[(size_t)MTOT * DIM],  g_kl[(size_t)MTOT * DIM];
__device__ float         g_v [(size_t)MTOT * DIM];
__device__ __nv_bfloat16 g_vth[(size_t)BATCH * DIM * SEQ], g_vtl[(size_t)BATCH * DIM * SEQ];
__device__ float         g_s [(size_t)BATCH * SEQ * SEQ];
__device__ __nv_bfloat16 g_ph[(size_t)BATCH * SEQ * SEQ], g_pl[(size_t)BATCH * SEQ * SEQ];

// ---------------------------------------------------------------------------
// PTX helpers (all supported on plain sm_103 target: ldmatrix / mma / cp.async)
// ---------------------------------------------------------------------------
__device__ __forceinline__ uint32_t smem_u32(const void* p) {
    return (uint32_t)__cvta_generic_to_shared(p);
}
__device__ __forceinline__ void ldsm_x4(uint32_t* r, uint32_t a) {
    asm volatile("ldmatrix.sync.aligned.m8n8.x4.shared.b16 {%0,%1,%2,%3},[%4];"
                 : "=r"(r[0]), "=r"(r[1]), "=r"(r[2]), "=r"(r[3]) : "r"(a));
}
__device__ __forceinline__ void mma16816(float* c,
                                         const uint32_t* a, uint32_t b0, uint32_t b1) {
    asm volatile(
        "mma.sync.aligned.m16n8k16.row.col.f32.bf16.bf16.f32 "
        "{%0,%1,%2,%3},{%4,%5,%6,%7},{%8,%9},{%0,%1,%2,%3};"
        : "+f"(c[0]), "+f"(c[1]), "+f"(c[2]), "+f"(c[3])
        : "r"(a[0]), "r"(a[1]), "r"(a[2]), "r"(a[3]), "r"(b0), "r"(b1));
}
__device__ __forceinline__ void cpa16(uint32_t dst, const void* src) {
    asm volatile("cp.async.cg.shared.global [%0], [%1], 16;" :: "r"(dst), "l"(src));
}
__device__ __forceinline__ void cpa_commit() {
    asm volatile("cp.async.commit_group;" ::: "memory");
}
template<int N>
__device__ __forceinline__ void cpa_wait() {
    asm volatile("cp.async.wait_group %0;" :: "n"(N) : "memory");
}

// fp32 pair -> (hi, lo) bf16x2 packed words.  x = hi + lo + O(2^-17 |x|)
__device__ __forceinline__ void split_pack(float x, float y, uint32_t& hi, uint32_t& lo) {
    __nv_bfloat16 hx = __float2bfloat16(x);
    __nv_bfloat16 hy = __float2bfloat16(y);
    __nv_bfloat162 h2; h2.x = hx; h2.y = hy;
    __nv_bfloat162 l2;
    l2.x = __float2bfloat16(x - __bfloat162float(hx));
    l2.y = __float2bfloat16(y - __bfloat162float(hy));
    hi = *reinterpret_cast<uint32_t*>(&h2);
    lo = *reinterpret_cast<uint32_t*>(&l2);
}

// ---------------------------------------------------------------------------
// Split-bf16 HMMA GEMM:  C[M,N] = (Ah+Al) @ (Bh+Bl)^T (+bias), fp32 accum.
//   A: [M,K] row-major bf16 (K-major).  B: [N,K] row-major bf16 (K-major).
// CTA tile 128(m) x 256(n), K-chunk 32, 3-stage cp.async ring, 512 threads.
// 16 warps = 4(m) x 4(n); warp tile 32 x 64.
// OUT=0: fp32 C.  OUT=1: split bf16 -> Ch, Cl.   blockIdx.z = batch.
// ---------------------------------------------------------------------------
constexpr int LDROW   = 80;                       // bytes/row: 32 bf16 + 8 pad
constexpr int OFF_AH  = 0;                        // 128 rows
constexpr int OFF_AL  = 128 * LDROW;              // 10240
constexpr int OFF_BH  = 2 * 128 * LDROW;          // 20480, 256 rows
constexpr int OFF_BL  = OFF_BH + 256 * LDROW;     // 40960
constexpr int STAGE_B = OFF_BL + 256 * LDROW;     // 61440
constexpr int NSTAGE  = 3;
constexpr size_t GSMEM = (size_t)NSTAGE * STAGE_B;  // 184320 B

template<int OUT, bool BIAS>
__global__ __launch_bounds__(512)
void mma2_gemm(const __nv_bfloat16* __restrict__ Ah, const __nv_bfloat16* __restrict__ Al,
               const __nv_bfloat16* __restrict__ Bh, const __nv_bfloat16* __restrict__ Bl,
               const float* __restrict__ bias,
               float* __restrict__ C,
               __nv_bfloat16* __restrict__ Ch, __nv_bfloat16* __restrict__ Cl,
               int N, int K, size_t sA, size_t sB, size_t sC)
{
    extern __shared__ char sm[];
    const uint32_t sbase = smem_u32(sm);
    const int tid  = threadIdx.x;
    const int lane = tid & 31;
    const int warp = tid >> 5;
    const int brow = blockIdx.y * 128;
    const int bcol = blockIdx.x * 256;
    const size_t bz = blockIdx.z;
    const int mw = (warp & 3) * 32;
    const int nw = (warp >> 2) * 64;

    // ---- producer (cp.async) per-thread constants: 6 x 16B chunks / stage ----
    const int rA = tid >> 2;            // 0..127
    const int c8 = tid & 3;             // 16B chunk within 64B row
    const __nv_bfloat16* pAh = Ah + bz * sA + (size_t)(brow + rA) * K + c8 * 8;
    const __nv_bfloat16* pAl = Al + bz * sA + (size_t)(brow + rA) * K + c8 * 8;
    const __nv_bfloat16* pBh = Bh + bz * sB + (size_t)(bcol + rA) * K + c8 * 8;
    const __nv_bfloat16* pBl = Bl + bz * sB + (size_t)(bcol + rA) * K + c8 * 8;
    const size_t bskip = (size_t)128 * K;
    const uint32_t dA = (uint32_t)rA * LDROW + c8 * 16;

    float acc[2][8][4] = {};

    // ---- prologue: stages 0 and 1 ----
    #pragma unroll
    for (int p = 0; p < 2; p++) {
        const uint32_t sb = sbase + p * STAGE_B;
        const int k0 = p * 32;
        cpa16(sb + OFF_AH + dA, pAh + k0);
        cpa16(sb + OFF_AL + dA, pAl + k0);
        cpa16(sb + OFF_BH + dA, pBh + k0);
        cpa16(sb + OFF_BH + dA + 128 * LDROW, pBh + bskip + k0);
        cpa16(sb + OFF_BL + dA, pBl + k0);
        cpa16(sb + OFF_BL + dA + 128 * LDROW, pBl + bskip + k0);
        cpa_commit();
    }

    // ---- consumer (ldmatrix) lane constants ----
    const int r8      = lane & 7;
    const int aRowOff = r8 + ((lane >> 3) & 1) * 8;   // + mw + i*16
    const int aColOff = ((lane >> 4) & 1) * 8;        // + ks
    const int bRowOff = r8 + ((lane >> 4) & 1) * 8;   // + nw + jp*16
    const int bColOff = ((lane >> 3) & 1) * 8;        // + ks

    const int nt = K / 32;
    for (int t = 0; t < nt; t++) {
        cpa_wait<1>();
        __syncthreads();
        const uint32_t sb = sbase + (t % 3) * STAGE_B;

        #pragma unroll
        for (int ks = 0; ks < 32; ks += 16) {
            uint32_t ah[2][4], al[2][4];
            #pragma unroll
            for (int i = 0; i < 2; i++) {
                const uint32_t ao = (uint32_t)(mw + i * 16 + aRowOff) * LDROW
                                  + (ks + aColOff) * 2;
                ldsm_x4(ah[i], sb + OFF_AH + ao);
                ldsm_x4(al[i], sb + OFF_AL + ao);
            }
            #pragma unroll
            for (int jp = 0; jp < 4; jp++) {
                uint32_t bh[4], bl[4];
                const uint32_t bo = (uint32_t)(nw + jp * 16 + bRowOff) * LDROW
                                  + (ks + bColOff) * 2;
                ldsm_x4(bh, sb + OFF_BH + bo);
                ldsm_x4(bl, sb + OFF_BL + bo);
                #pragma unroll
                for (int i = 0; i < 2; i++) {
                    mma16816(acc[i][2 * jp],     ah[i], bh[0], bh[1]);
                    mma16816(acc[i][2 * jp + 1], ah[i], bh[2], bh[3]);
                    mma16816(acc[i][2 * jp],     ah[i], bl[0], bl[1]);
                    mma16816(acc[i][2 * jp + 1], ah[i], bl[2], bl[3]);
                    mma16816(acc[i][2 * jp],     al[i], bh[0], bh[1]);
                    mma16816(acc[i][2 * jp + 1], al[i], bh[2], bh[3]);
                }
            }
        }

        // stage (t+2)%3 was last computed at iter t-1; everyone passed this
        // iter's barrier after finishing it, so the refill is WAR-safe.
        if (t + 2 < nt) {
            const uint32_t sbn = sbase + ((t + 2) % 3) * STAGE_B;
            const int k0 = (t + 2) * 32;
            cpa16(sbn + OFF_AH + dA, pAh + k0);
            cpa16(sbn + OFF_AL + dA, pAl + k0);
            cpa16(sbn + OFF_BH + dA, pBh + k0);
            cpa16(sbn + OFF_BH + dA + 128 * LDROW, pBh + bskip + k0);
            cpa16(sbn + OFF_BL + dA, pBl + k0);
            cpa16(sbn + OFF_BL + dA + 128 * LDROW, pBl + bskip + k0);
        }
        cpa_commit();   // always commit: keeps wait_group accounting uniform
    }

    // ---- epilogue: acc[i][j] -> (m = brow+mw+i*16+{g, g+8}, n = bcol+nw+j*8+2*tg)
    const int g  = lane >> 2;
    const int tg = lane & 3;
    #pragma unroll
    for (int i = 0; i < 2; i++) {
        #pragma unroll
        for (int j = 0; j < 8; j++) {
            const int m = brow + mw + i * 16 + g;
            const int n = bcol + nw + j * 8 + tg * 2;
            float b0 = 0.f, b1 = 0.f;
            if (BIAS) { b0 = bias[n]; b1 = bias[n + 1]; }
            const float v00 = acc[i][j][0] + b0, v01 = acc[i][j][1] + b1;
            const float v10 = acc[i][j][2] + b0, v11 = acc[i][j][3] + b1;
            if (OUT == 0) {
                float* Cp = C + bz * sC;
                *(float2*)&Cp[(size_t)m * N + n]       = make_float2(v00, v01);
                *(float2*)&Cp[(size_t)(m + 8) * N + n] = make_float2(v10, v11);
            } else {
                uint32_t h0, l0, h1, l1;
                split_pack(v00, v01, h0, l0);
                split_pack(v10, v11, h1, l1);
                *(uint32_t*)&Ch[(size_t)m * N + n]       = h0;
                *(uint32_t*)&Cl[(size_t)m * N + n]       = l0;
                *(uint32_t*)&Ch[(size_t)(m + 8) * N + n] = h1;
                *(uint32_t*)&Cl[(size_t)(m + 8) * N + n] = l1;
            }
        }
    }
}

// ---------------------------------------------------------------------------
// convert_x: fp32 -> (hi, lo) bf16, elementwise.  One float4 per thread.
// ---------------------------------------------------------------------------
__global__ __launch_bounds__(256)
void convert_x(const float4* __restrict__ X, uint32_t* __restrict__ Xh,
               uint32_t* __restrict__ Xl)
{
    const size_t i = (size_t)blockIdx.x * 256 + threadIdx.x;
    float4 v = X[i];
    uint32_t h0, l0, h1, l1;
    split_pack(v.x, v.y, h0, l0);
    split_pack(v.z, v.w, h1, l1);
    Xh[2 * i] = h0; Xh[2 * i + 1] = h1;
    Xl[2 * i] = l0; Xl[2 * i + 1] = l1;
}

// ---------------------------------------------------------------------------
// convert_wt: W [1024(in),1024(out)] fp32 -> Wt hi/lo bf16 [out,in] (transpose).
// ---------------------------------------------------------------------------
__global__ __launch_bounds__(256)
void convert_wt(const float* __restrict__ W, __nv_bfloat16* __restrict__ Th,
                __nv_bfloat16* __restrict__ Tl)
{
    __shared__ float t[32][33];
    const int bx = blockIdx.x * 32, by = blockIdx.y * 32;
    const int x = threadIdx.x, y = threadIdx.y;
    #pragma unroll
    for (int r = 0; r < 4; r++)
        t[y + 8 * r][x] = W[(size_t)(by + y + 8 * r) * DIM + bx + x];
    __syncthreads();
    #pragma unroll
    for (int r = 0; r < 4; r++) {
        float v = t[x][y + 8 * r];
        __nv_bfloat16 h = __float2bfloat16(v);
        __nv_bfloat16 l = __float2bfloat16(v - __bfloat162float(h));
        const size_t o = (size_t)(bx + y + 8 * r) * DIM + by + x;
        Th[o] = h; Tl[o] = l;
    }
}

// ---------------------------------------------------------------------------
// transpose_v: v [b,2048,1024] fp32 -> vt hi/lo bf16 [b,1024,2048].
// ---------------------------------------------------------------------------
__global__ __launch_bounds__(256)
void transpose_v(const float* __restrict__ V, __nv_bfloat16* __restrict__ Th,
                 __nv_bfloat16* __restrict__ Tl)
{
    __shared__ float t[32][33];
    const int bx = blockIdx.x * 32;          // s
    const int by = blockIdx.y * 32;          // d
    const size_t bofI = (size_t)blockIdx.z * SEQ * DIM;
    const size_t bofO = (size_t)blockIdx.z * DIM * SEQ;
    const int x = threadIdx.x, y = threadIdx.y;
    #pragma unroll
    for (int r = 0; r < 4; r++)
        t[y + 8 * r][x] = V[bofI + (size_t)(bx + y + 8 * r) * DIM + by + x];
    __syncthreads();
    #pragma unroll
    for (int r = 0; r < 4; r++) {
        float v = t[x][y + 8 * r];
        __nv_bfloat16 h = __float2bfloat16(v);
        __nv_bfloat16 l = __float2bfloat16(v - __bfloat162float(h));
        const size_t o = bofO + (size_t)(by + y + 8 * r) * SEQ + bx + x;
        Th[o] = h; Tl[o] = l;
    }
}

// ---------------------------------------------------------------------------
// Row softmax, length 2048, one warp per row; outputs split hi/lo bf16.
// ---------------------------------------------------------------------------
__global__ __launch_bounds__(256)
void softmax_split(const float* __restrict__ S, __nv_bfloat16* __restrict__ Ph,
                   __nv_bfloat16* __restrict__ Pl)
{
    const int lane = threadIdx.x & 31;
    const int w    = threadIdx.x >> 5;
    const size_t row = (size_t)blockIdx.x * 8 + w;
    const float4* p = reinterpret_cast<const float4*>(S + row * 2048);

    float4 v[16];
    #pragma unroll
    for (int i = 0; i < 16; i++) v[i] = p[lane + 32 * i];

    float m = -3.0e38f;
    #pragma unroll
    for (int i = 0; i < 16; i++)
        m = fmaxf(m, fmaxf(fmaxf(v[i].x, v[i].y), fmaxf(v[i].z, v[i].w)));
    #pragma unroll
    for (int o = 16; o; o >>= 1) m = fmaxf(m, __shfl_xor_sync(0xffffffffu, m, o));

    float s = 0.f;
    #pragma unroll
    for (int i = 0; i < 16; i++) {
        v[i].x = __expf(v[i].x - m); v[i].y = __expf(v[i].y - m);
        v[i].z = __expf(v[i].z - m); v[i].w = __expf(v[i].w - m);
        s += v[i].x + v[i].y + v[i].z + v[i].w;
    }
    #pragma unroll
    for (int o = 16; o; o >>= 1) s += __shfl_xor_sync(0xffffffffu, s, o);

    const float inv = 1.0f / s;
    uint32_t* hp = reinterpret_cast<uint32_t*>(Ph) + row * 1024;
    uint32_t* lp = reinterpret_cast<uint32_t*>(Pl) + row * 1024;
    #pragma unroll
    for (int i = 0; i < 16; i++) {
        uint32_t h0, l0, h1, l1;
        split_pack(v[i].x * inv, v[i].y * inv, h0, l0);
        split_pack(v[i].z * inv, v[i].w * inv, h1, l1);
        const int c = lane + 32 * i;
        hp[2 * c] = h0; hp[2 * c + 1] = h1;
        lp[2 * c] = l0; lp[2 * c + 1] = l1;
    }
}

// ---------------------------------------------------------------------------
// Launch sequence.
// Inputs (metadata order): x, Wq, bq, Wk, bk, Wv, bv.  Output: [B,S,D] fp32.
// ---------------------------------------------------------------------------
extern "C" void kernel_launch(void* const* d_in, const int* in_sizes, int n_in,
                              void* d_out, int out_size)
{
    const float* x  = (const float*)d_in[0];
    const float* Wq = (const float*)d_in[1];
    const float* bq = (const float*)d_in[2];
    const float* Wk = (const float*)d_in[3];
    const float* bk = (const float*)d_in[4];
    const float* Wv = (const float*)d_in[5];
    const float* bv = (const float*)d_in[6];
    float* out = (float*)d_out;

    __nv_bfloat16 *xh, *xl, *wth, *wtl, *qh, *ql, *kh, *kl, *vth, *vtl, *ph, *pl;
    float *v, *s;
    cudaGetSymbolAddress((void**)&xh,  g_xh);  cudaGetSymbolAddress((void**)&xl,  g_xl);
    cudaGetSymbolAddress((void**)&wth, g_wth); cudaGetSymbolAddress((void**)&wtl, g_wtl);
    cudaGetSymbolAddress((void**)&qh,  g_qh);  cudaGetSymbolAddress((void**)&ql,  g_ql);
    cudaGetSymbolAddress((void**)&kh,  g_kh);  cudaGetSymbolAddress((void**)&kl,  g_kl);
    cudaGetSymbolAddress((void**)&v,   g_v);
    cudaGetSymbolAddress((void**)&vth, g_vth); cudaGetSymbolAddress((void**)&vtl, g_vtl);
    cudaGetSymbolAddress((void**)&s,   g_s);
    cudaGetSymbolAddress((void**)&ph,  g_ph);  cudaGetSymbolAddress((void**)&pl,  g_pl);

    cudaFuncSetAttribute(mma2_gemm<1, true>,
                         cudaFuncAttributeMaxDynamicSharedMemorySize, (int)GSMEM);
    cudaFuncSetAttribute(mma2_gemm<0, true>,
                         cudaFuncAttributeMaxDynamicSharedMemorySize, (int)GSMEM);
    cudaFuncSetAttribute(mma2_gemm<0, false>,
                         cudaFuncAttributeMaxDynamicSharedMemorySize, (int)GSMEM);

    const dim3 blk(512);
    const size_t WOFF = (size_t)DIM * DIM;
    const dim3 bwt(32, 8);

    // 1) conversions
    convert_x<<<(MTOT * DIM) / (256 * 4), 256>>>((const float4*)x, (uint32_t*)xh, (uint32_t*)xl);
    const dim3 gwt(DIM / 32, DIM / 32);
    convert_wt<<<gwt, bwt>>>(Wq, wth,            wtl);
    convert_wt<<<gwt, bwt>>>(Wk, wth + WOFF,     wtl + WOFF);
    convert_wt<<<gwt, bwt>>>(Wv, wth + 2 * WOFF, wtl + 2 * WOFF);

    // 2) projections: [8192,1024] @ Wt^T + bias   (tile 128x256)
    const dim3 gp(DIM / 256, MTOT / 128);                    // (4, 64)
    mma2_gemm<1, true><<<gp, blk, GSMEM>>>(xh, xl, wth,            wtl,            bq,
                                           nullptr, qh, ql, DIM, DIM, 0, 0, 0);
    mma2_gemm<1, true><<<gp, blk, GSMEM>>>(xh, xl, wth + WOFF,     wtl + WOFF,     bk,
                                           nullptr, kh, kl, DIM, DIM, 0, 0, 0);
    mma2_gemm<0, true><<<gp, blk, GSMEM>>>(xh, xl, wth + 2 * WOFF, wtl + 2 * WOFF, bv,
                                           v, nullptr, nullptr, DIM, DIM, 0, 0, 0);

    // 3) V transpose + split
    transpose_v<<<dim3(SEQ / 32, DIM / 32, BATCH), bwt>>>(v, vth, vtl);

    // 4) scores = Q @ K^T per batch -> fp32 S
    const dim3 gs(SEQ / 256, SEQ / 128, BATCH);              // (8, 16, 4)
    mma2_gemm<0, false><<<gs, blk, GSMEM>>>(qh, ql, kh, kl, nullptr,
                                            s, nullptr, nullptr, SEQ, DIM,
                                            (size_t)SEQ * DIM, (size_t)SEQ * DIM,
                                            (size_t)SEQ * SEQ);

    // 5) softmax -> P hi/lo
    softmax_split<<<MTOT / 8, 256>>>(s, ph, pl);

    // 6) out = P @ V^T per batch
    const dim3 go(DIM / 256, SEQ / 128, BATCH);              // (4, 16, 4)
    mma2_gemm<0, false><<<go, blk, GSMEM>>>(ph, pl, vth, vtl, nullptr,
                                            out, nullptr, nullptr, DIM, SEQ,
                                            (size_t)SEQ * SEQ, (size_t)DIM * SEQ,
                                            (size_t)SEQ * DIM);
}

// round 13
// speedup vs baseline: 3.0413x; 1.1487x over previous
#include <cuda_runtime.h>
#include <cuda_bf16.h>
#include <cuda_fp16.h>
#include <cstdint>

// Problem shape (fixed per reference): B=4, S=2048, D=1024, fp32.
#define BATCH 4
#define SEQ   2048
#define DIM   1024
#define MTOT  (BATCH * SEQ)          // 8192

// ---------------------------------------------------------------------------
// Scratch (device globals: allocation-guard safe).
// ---------------------------------------------------------------------------
__device__ __nv_bfloat16 g_xh[(size_t)MTOT * DIM], g_xl[(size_t)MTOT * DIM];
__device__ __half        g_x16[(size_t)MTOT * DIM];
__device__ __nv_bfloat16 g_wth[(size_t)2 * DIM * DIM], g_wtl[(size_t)2 * DIM * DIM];
__device__ __half        g_wv16[(size_t)DIM * DIM];
__device__ __nv_bfloat16 g_qh[(size_t)MTOT * DIM],  g_ql[(size_t)MTOT * DIM];
__device__ __nv_bfloat16 g_kh[(size_t)MTOT * DIM],  g_kl[(size_t)MTOT * DIM];
__device__ float         g_v [(size_t)MTOT * DIM];
__device__ __half        g_vth[(size_t)BATCH * DIM * SEQ], g_vtl[(size_t)BATCH * DIM * SEQ];
__device__ float         g_s [(size_t)BATCH * SEQ * SEQ];
__device__ __half        g_p16[(size_t)BATCH * SEQ * SEQ];

// ---------------------------------------------------------------------------
// PTX helpers (ldmatrix / mma / cp.async: all valid on plain sm_103 target)
// ---------------------------------------------------------------------------
__device__ __forceinline__ uint32_t smem_u32(const void* p) {
    return (uint32_t)__cvta_generic_to_shared(p);
}
__device__ __forceinline__ void ldsm_x4(uint32_t* r, uint32_t a) {
    asm volatile("ldmatrix.sync.aligned.m8n8.x4.shared.b16 {%0,%1,%2,%3},[%4];"
                 : "=r"(r[0]), "=r"(r[1]), "=r"(r[2]), "=r"(r[3]) : "r"(a));
}
template<bool F16>
__device__ __forceinline__ void mma_any(float* c, const uint32_t* a,
                                        uint32_t b0, uint32_t b1) {
    if (F16)
        asm volatile(
            "mma.sync.aligned.m16n8k16.row.col.f32.f16.f16.f32 "
            "{%0,%1,%2,%3},{%4,%5,%6,%7},{%8,%9},{%0,%1,%2,%3};"
            : "+f"(c[0]), "+f"(c[1]), "+f"(c[2]), "+f"(c[3])
            : "r"(a[0]), "r"(a[1]), "r"(a[2]), "r"(a[3]), "r"(b0), "r"(b1));
    else
        asm volatile(
            "mma.sync.aligned.m16n8k16.row.col.f32.bf16.bf16.f32 "
            "{%0,%1,%2,%3},{%4,%5,%6,%7},{%8,%9},{%0,%1,%2,%3};"
            : "+f"(c[0]), "+f"(c[1]), "+f"(c[2]), "+f"(c[3])
            : "r"(a[0]), "r"(a[1]), "r"(a[2]), "r"(a[3]), "r"(b0), "r"(b1));
}
__device__ __forceinline__ void cpa16(uint32_t dst, const void* src) {
    asm volatile("cp.async.cg.shared.global [%0], [%1], 16;" :: "r"(dst), "l"(src));
}
__device__ __forceinline__ void cpa_commit() {
    asm volatile("cp.async.commit_group;" ::: "memory");
}
template<int N>
__device__ __forceinline__ void cpa_wait() {
    asm volatile("cp.async.wait_group %0;" :: "n"(N) : "memory");
}

// fp32 pair -> (hi, lo) bf16x2 packed words.  x = hi + lo + O(2^-17 |x|)
__device__ __forceinline__ void split_pack(float x, float y, uint32_t& hi, uint32_t& lo) {
    __nv_bfloat16 hx = __float2bfloat16(x);
    __nv_bfloat16 hy = __float2bfloat16(y);
    __nv_bfloat162 h2; h2.x = hx; h2.y = hy;
    __nv_bfloat162 l2;
    l2.x = __float2bfloat16(x - __bfloat162float(hx));
    l2.y = __float2bfloat16(y - __bfloat162float(hy));
    hi = *reinterpret_cast<uint32_t*>(&h2);
    lo = *reinterpret_cast<uint32_t*>(&l2);
}

// ---------------------------------------------------------------------------
// Generic split HMMA GEMM.  C[M,N] = A @ B^T (+bias), fp32 accum.
//   PROD=3: A=(A0+A1), B=(B0+B1), 3 cross products (bf16 "fp32-like").
//   PROD=2: A=A0 single, B=(B0+B1), 2 products.
//   PROD=1: A=A0, B=B0 single product.
//   F16 selects fp16 vs bf16 mma.  All operands [rows, K] row-major, 2B elems.
// CTA tile 128(m) x 256(n), K-chunk 32, 3-stage cp.async ring, 512 threads.
// 16 warps = 4(m) x 4(n); warp tile 32 x 64.
// OUT=0: fp32 C (+bias).  OUT=1: split bf16 -> Ch, Cl (+bias).
// ---------------------------------------------------------------------------
constexpr int LDROW = 80;                     // bytes/row: 32 elems + 8 pad

// stage bytes for a given PROD (shared between kernel and launcher!)
// NOTE: must be __host__ __device__ — harness nvcc has no --expt-relaxed-constexpr.
__host__ __device__ constexpr int stage_bytes(int prod) {
    return (((prod == 3) ? 2 : 1) * 128 + ((prod == 1) ? 1 : 2) * 256) * LDROW;
}

template<int PROD, bool F16, int OUT, bool BIAS>
__global__ __launch_bounds__(512)
void g_gemm(const uint16_t* __restrict__ A0, const uint16_t* __restrict__ A1,
            const uint16_t* __restrict__ B0, const uint16_t* __restrict__ B1,
            const float* __restrict__ bias,
            float* __restrict__ C,
            __nv_bfloat16* __restrict__ Ch, __nv_bfloat16* __restrict__ Cl,
            int N, int K, size_t sA, size_t sB, size_t sC)
{
    constexpr int NA = (PROD == 3) ? 2 : 1;
    constexpr int NB = (PROD == 1) ? 1 : 2;
    constexpr int OFF_A0 = 0;
    constexpr int OFF_A1 = 128 * LDROW;
    constexpr int OFF_B0 = NA * 128 * LDROW;
    constexpr int OFF_B1 = OFF_B0 + 256 * LDROW;
    constexpr int STAGE  = stage_bytes(PROD);

    extern __shared__ char sm[];
    const uint32_t sbase = smem_u32(sm);
    const int tid  = threadIdx.x;
    const int lane = tid & 31;
    const int warp = tid >> 5;
    const int brow = blockIdx.y * 128;
    const int bcol = blockIdx.x * 256;
    const size_t bz = blockIdx.z;
    const int mw = (warp & 3) * 32;
    const int nw = (warp >> 2) * 64;

    // ---- producer constants ----
    const int rA = tid >> 2;            // 0..127
    const int c8 = tid & 3;             // 16B chunk within 64B span
    const uint16_t* pA0 = A0 + bz * sA + (size_t)(brow + rA) * K + c8 * 8;
    const uint16_t* pA1 = A1 + bz * sA + (size_t)(brow + rA) * K + c8 * 8;
    const uint16_t* pB0 = B0 + bz * sB + (size_t)(bcol + rA) * K + c8 * 8;
    const uint16_t* pB1 = B1 + bz * sB + (size_t)(bcol + rA) * K + c8 * 8;
    const size_t bskip = (size_t)128 * K;
    const uint32_t dA = (uint32_t)rA * LDROW + c8 * 16;

    float acc[2][8][4] = {};

    // ---- prologue: stages 0 and 1 ----
    #pragma unroll
    for (int p = 0; p < 2; p++) {
        const uint32_t sb = sbase + p * STAGE;
        const int k0 = p * 32;
        cpa16(sb + OFF_A0 + dA, pA0 + k0);
        if (NA == 2) cpa16(sb + OFF_A1 + dA, pA1 + k0);
        cpa16(sb + OFF_B0 + dA, pB0 + k0);
        cpa16(sb + OFF_B0 + dA + 128 * LDROW, pB0 + bskip + k0);
        if (NB == 2) {
            cpa16(sb + OFF_B1 + dA, pB1 + k0);
            cpa16(sb + OFF_B1 + dA + 128 * LDROW, pB1 + bskip + k0);
        }
        cpa_commit();
    }

    // ---- consumer lane constants ----
    const int r8      = lane & 7;
    const int aRowOff = r8 + ((lane >> 3) & 1) * 8;
    const int aColOff = ((lane >> 4) & 1) * 8;
    const int bRowOff = r8 + ((lane >> 4) & 1) * 8;
    const int bColOff = ((lane >> 3) & 1) * 8;

    const int nt = K / 32;
    for (int t = 0; t < nt; t++) {
        cpa_wait<1>();
        __syncthreads();
        const uint32_t sb = sbase + (t % 3) * STAGE;

        #pragma unroll
        for (int ks = 0; ks < 32; ks += 16) {
            uint32_t a0[2][4], a1[2][4];
            #pragma unroll
            for (int i = 0; i < 2; i++) {
                const uint32_t ao = (uint32_t)(mw + i * 16 + aRowOff) * LDROW
                                  + (ks + aColOff) * 2;
                ldsm_x4(a0[i], sb + OFF_A0 + ao);
                if (NA == 2) ldsm_x4(a1[i], sb + OFF_A1 + ao);
            }
            #pragma unroll
            for (int jp = 0; jp < 4; jp++) {
                uint32_t b0[4], b1[4];
                const uint32_t bo = (uint32_t)(nw + jp * 16 + bRowOff) * LDROW
                                  + (ks + bColOff) * 2;
                ldsm_x4(b0, sb + OFF_B0 + bo);
                if (NB == 2) ldsm_x4(b1, sb + OFF_B1 + bo);
                #pragma unroll
                for (int i = 0; i < 2; i++) {
                    mma_any<F16>(acc[i][2 * jp],     a0[i], b0[0], b0[1]);
                    mma_any<F16>(acc[i][2 * jp + 1], a0[i], b0[2], b0[3]);
                    if (NB == 2) {
                        mma_any<F16>(acc[i][2 * jp],     a0[i], b1[0], b1[1]);
                        mma_any<F16>(acc[i][2 * jp + 1], a0[i], b1[2], b1[3]);
                    }
                    if (NA == 2) {
                        mma_any<F16>(acc[i][2 * jp],     a1[i], b0[0], b0[1]);
                        mma_any<F16>(acc[i][2 * jp + 1], a1[i], b0[2], b0[3]);
                    }
                }
            }
        }

        // stage (t+2)%3 was last consumed at iter t-1; the barrier above makes
        // this refill WAR-safe.
        if (t + 2 < nt) {
            const uint32_t sbn = sbase + ((t + 2) % 3) * STAGE;
            const int k0 = (t + 2) * 32;
            cpa16(sbn + OFF_A0 + dA, pA0 + k0);
            if (NA == 2) cpa16(sbn + OFF_A1 + dA, pA1 + k0);
            cpa16(sbn + OFF_B0 + dA, pB0 + k0);
            cpa16(sbn + OFF_B0 + dA + 128 * LDROW, pB0 + bskip + k0);
            if (NB == 2) {
                cpa16(sbn + OFF_B1 + dA, pB1 + k0);
                cpa16(sbn + OFF_B1 + dA + 128 * LDROW, pB1 + bskip + k0);
            }
        }
        cpa_commit();   // always commit: uniform wait_group accounting
    }

    // ---- epilogue ----
    const int g  = lane >> 2;
    const int tg = lane & 3;
    #pragma unroll
    for (int i = 0; i < 2; i++) {
        #pragma unroll
        for (int j = 0; j < 8; j++) {
            const int m = brow + mw + i * 16 + g;
            const int n = bcol + nw + j * 8 + tg * 2;
            float b0 = 0.f, b1 = 0.f;
            if (BIAS) { b0 = bias[n]; b1 = bias[n + 1]; }
            const float v00 = acc[i][j][0] + b0, v01 = acc[i][j][1] + b1;
            const float v10 = acc[i][j][2] + b0, v11 = acc[i][j][3] + b1;
            if (OUT == 0) {
                float* Cp = C + bz * sC;
                *(float2*)&Cp[(size_t)m * N + n]       = make_float2(v00, v01);
                *(float2*)&Cp[(size_t)(m + 8) * N + n] = make_float2(v10, v11);
            } else {
                uint32_t h0, l0, h1, l1;
                split_pack(v00, v01, h0, l0);
                split_pack(v10, v11, h1, l1);
                *(uint32_t*)&Ch[(size_t)m * N + n]       = h0;
                *(uint32_t*)&Cl[(size_t)m * N + n]       = l0;
                *(uint32_t*)&Ch[(size_t)(m + 8) * N + n] = h1;
                *(uint32_t*)&Cl[(size_t)(m + 8) * N + n] = l1;
            }
        }
    }
}

// ---------------------------------------------------------------------------
// convert_x: fp32 -> bf16 hi/lo split AND fp16 single, one pass over x.
// ---------------------------------------------------------------------------
__global__ __launch_bounds__(256)
void convert_x(const float4* __restrict__ X, uint32_t* __restrict__ Xh,
               uint32_t* __restrict__ Xl, uint32_t* __restrict__ X16)
{
    const size_t i = (size_t)blockIdx.x * 256 + threadIdx.x;
    float4 v = X[i];
    uint32_t h0, l0, h1, l1;
    split_pack(v.x, v.y, h0, l0);
    split_pack(v.z, v.w, h1, l1);
    Xh[2 * i] = h0; Xh[2 * i + 1] = h1;
    Xl[2 * i] = l0; Xl[2 * i + 1] = l1;
    __half2 p0 = __floats2half2_rn(v.x, v.y);
    __half2 p1 = __floats2half2_rn(v.z, v.w);
    X16[2 * i]     = *reinterpret_cast<uint32_t*>(&p0);
    X16[2 * i + 1] = *reinterpret_cast<uint32_t*>(&p1);
}

// ---------------------------------------------------------------------------
// convert_wt: W [in,out] fp32 -> Wt [out,in] bf16 hi/lo (transpose + split).
// ---------------------------------------------------------------------------
__global__ __launch_bounds__(256)
void convert_wt(const float* __restrict__ W, __nv_bfloat16* __restrict__ Th,
                __nv_bfloat16* __restrict__ Tl)
{
    __shared__ float t[32][33];
    const int bx = blockIdx.x * 32, by = blockIdx.y * 32;
    const int x = threadIdx.x, y = threadIdx.y;
    #pragma unroll
    for (int r = 0; r < 4; r++)
        t[y + 8 * r][x] = W[(size_t)(by + y + 8 * r) * DIM + bx + x];
    __syncthreads();
    #pragma unroll
    for (int r = 0; r < 4; r++) {
        float v = t[x][y + 8 * r];
        __nv_bfloat16 h = __float2bfloat16(v);
        __nv_bfloat16 l = __float2bfloat16(v - __bfloat162float(h));
        const size_t o = (size_t)(bx + y + 8 * r) * DIM + by + x;
        Th[o] = h; Tl[o] = l;
    }
}

// convert_wt_f16: W [in,out] fp32 -> Wt [out,in] fp16 single.
__global__ __launch_bounds__(256)
void convert_wt_f16(const float* __restrict__ W, __half* __restrict__ T)
{
    __shared__ float t[32][33];
    const int bx = blockIdx.x * 32, by = blockIdx.y * 32;
    const int x = threadIdx.x, y = threadIdx.y;
    #pragma unroll
    for (int r = 0; r < 4; r++)
        t[y + 8 * r][x] = W[(size_t)(by + y + 8 * r) * DIM + bx + x];
    __syncthreads();
    #pragma unroll
    for (int r = 0; r < 4; r++)
        T[(size_t)(bx + y + 8 * r) * DIM + by + x] = __float2half(t[x][y + 8 * r]);
}

// ---------------------------------------------------------------------------
// transpose_v: v [b,2048,1024] fp32 -> vt hi/lo FP16 [b,1024,2048].
// ---------------------------------------------------------------------------
__global__ __launch_bounds__(256)
void transpose_v(const float* __restrict__ V, __half* __restrict__ Th,
                 __half* __restrict__ Tl)
{
    __shared__ float t[32][33];
    const int bx = blockIdx.x * 32;          // s
    const int by = blockIdx.y * 32;          // d
    const size_t bofI = (size_t)blockIdx.z * SEQ * DIM;
    const size_t bofO = (size_t)blockIdx.z * DIM * SEQ;
    const int x = threadIdx.x, y = threadIdx.y;
    #pragma unroll
    for (int r = 0; r < 4; r++)
        t[y + 8 * r][x] = V[bofI + (size_t)(bx + y + 8 * r) * DIM + by + x];
    __syncthreads();
    #pragma unroll
    for (int r = 0; r < 4; r++) {
        float v = t[x][y + 8 * r];
        __half h = __float2half(v);
        __half l = __float2half(v - __half2float(h));
        const size_t o = bofO + (size_t)(by + y + 8 * r) * SEQ + bx + x;
        Th[o] = h; Tl[o] = l;
    }
}

// ---------------------------------------------------------------------------
// Row softmax, length 2048, one warp per row; outputs single fp16 P.
// ---------------------------------------------------------------------------
__global__ __launch_bounds__(256)
void softmax_f16(const float* __restrict__ S, __half* __restrict__ P)
{
    const int lane = threadIdx.x & 31;
    const int w    = threadIdx.x >> 5;
    const size_t row = (size_t)blockIdx.x * 8 + w;
    const float4* p = reinterpret_cast<const float4*>(S + row * 2048);

    float4 v[16];
    #pragma unroll
    for (int i = 0; i < 16; i++) v[i] = p[lane + 32 * i];

    float m = -3.0e38f;
    #pragma unroll
    for (int i = 0; i < 16; i++)
        m = fmaxf(m, fmaxf(fmaxf(v[i].x, v[i].y), fmaxf(v[i].z, v[i].w)));
    #pragma unroll
    for (int o = 16; o; o >>= 1) m = fmaxf(m, __shfl_xor_sync(0xffffffffu, m, o));

    float s = 0.f;
    #pragma unroll
    for (int i = 0; i < 16; i++) {
        v[i].x = __expf(v[i].x - m); v[i].y = __expf(v[i].y - m);
        v[i].z = __expf(v[i].z - m); v[i].w = __expf(v[i].w - m);
        s += v[i].x + v[i].y + v[i].z + v[i].w;
    }
    #pragma unroll
    for (int o = 16; o; o >>= 1) s += __shfl_xor_sync(0xffffffffu, s, o);

    const float inv = 1.0f / s;
    uint32_t* op = reinterpret_cast<uint32_t*>(P) + row * 1024;
    #pragma unroll
    for (int i = 0; i < 16; i++) {
        __half2 p0 = __floats2half2_rn(v[i].x * inv, v[i].y * inv);
        __half2 p1 = __floats2half2_rn(v[i].z * inv, v[i].w * inv);
        const int c = lane + 32 * i;
        op[2 * c]     = *reinterpret_cast<uint32_t*>(&p0);
        op[2 * c + 1] = *reinterpret_cast<uint32_t*>(&p1);
    }
}

// ---------------------------------------------------------------------------
// Launch sequence.
// Inputs (metadata order): x, Wq, bq, Wk, bk, Wv, bv.  Output: [B,S,D] fp32.
// ---------------------------------------------------------------------------
extern "C" void kernel_launch(void* const* d_in, const int* in_sizes, int n_in,
                              void* d_out, int out_size)
{
    const float* x  = (const float*)d_in[0];
    const float* Wq = (const float*)d_in[1];
    const float* bq = (const float*)d_in[2];
    const float* Wk = (const float*)d_in[3];
    const float* bk = (const float*)d_in[4];
    const float* Wv = (const float*)d_in[5];
    const float* bv = (const float*)d_in[6];
    float* out = (float*)d_out;

    __nv_bfloat16 *xh, *xl, *wth, *wtl, *qh, *ql, *kh, *kl;
    __half *x16, *wv16, *vth, *vtl, *p16;
    float *v, *s;
    cudaGetSymbolAddress((void**)&xh,   g_xh);  cudaGetSymbolAddress((void**)&xl,  g_xl);
    cudaGetSymbolAddress((void**)&x16,  g_x16);
    cudaGetSymbolAddress((void**)&wth,  g_wth); cudaGetSymbolAddress((void**)&wtl, g_wtl);
    cudaGetSymbolAddress((void**)&wv16, g_wv16);
    cudaGetSymbolAddress((void**)&qh,   g_qh);  cudaGetSymbolAddress((void**)&ql,  g_ql);
    cudaGetSymbolAddress((void**)&kh,   g_kh);  cudaGetSymbolAddress((void**)&kl,  g_kl);
    cudaGetSymbolAddress((void**)&v,    g_v);
    cudaGetSymbolAddress((void**)&vth,  g_vth); cudaGetSymbolAddress((void**)&vtl, g_vtl);
    cudaGetSymbolAddress((void**)&s,    g_s);
    cudaGetSymbolAddress((void**)&p16,  g_p16);

    // smem sizes per PROD — same stage_bytes() the kernel uses.
    const int SM3 = 3 * stage_bytes(3);   // 184320
    const int SM2 = 3 * stage_bytes(2);   // 153600
    const int SM1 = 3 * stage_bytes(1);   //  92160

    cudaFuncSetAttribute(g_gemm<3, false, 1, true>,
                         cudaFuncAttributeMaxDynamicSharedMemorySize, SM3);
    cudaFuncSetAttribute(g_gemm<3, false, 0, false>,
                         cudaFuncAttributeMaxDynamicSharedMemorySize, SM3);
    cudaFuncSetAttribute(g_gemm<1, true, 0, true>,
                         cudaFuncAttributeMaxDynamicSharedMemorySize, SM1);
    cudaFuncSetAttribute(g_gemm<2, true, 0, false>,
                         cudaFuncAttributeMaxDynamicSharedMemorySize, SM2);

    const dim3 blk(512);
    const size_t WOFF = (size_t)DIM * DIM;
    const dim3 bwt(32, 8);
    const dim3 gwt(DIM / 32, DIM / 32);

    // 1) conversions
    convert_x<<<(MTOT * DIM) / (256 * 4), 256>>>((const float4*)x,
        (uint32_t*)xh, (uint32_t*)xl, (uint32_t*)x16);
    convert_wt<<<gwt, bwt>>>(Wq, wth,        wtl);
    convert_wt<<<gwt, bwt>>>(Wk, wth + WOFF, wtl + WOFF);
    convert_wt_f16<<<gwt, bwt>>>(Wv, wv16);

    // 2) projections
    const dim3 gp(DIM / 256, MTOT / 128);                    // (4, 64)
    g_gemm<3, false, 1, true><<<gp, blk, SM3>>>(
        (const uint16_t*)xh, (const uint16_t*)xl,
        (const uint16_t*)wth, (const uint16_t*)wtl, bq,
        nullptr, qh, ql, DIM, DIM, 0, 0, 0);
    g_gemm<3, false, 1, true><<<gp, blk, SM3>>>(
        (const uint16_t*)xh, (const uint16_t*)xl,
        (const uint16_t*)(wth + WOFF), (const uint16_t*)(wtl + WOFF), bk,
        nullptr, kh, kl, DIM, DIM, 0, 0, 0);
    g_gemm<1, true, 0, true><<<gp, blk, SM1>>>(
        (const uint16_t*)x16, nullptr,
        (const uint16_t*)wv16, nullptr, bv,
        v, nullptr, nullptr, DIM, DIM, 0, 0, 0);

    // 3) V transpose + fp16 split
    transpose_v<<<dim3(SEQ / 32, DIM / 32, BATCH), bwt>>>(v, vth, vtl);

    // 4) scores = Q @ K^T per batch -> fp32 S  (bf16 3-product)
    const dim3 gs(SEQ / 256, SEQ / 128, BATCH);              // (8, 16, 4)
    g_gemm<3, false, 0, false><<<gs, blk, SM3>>>(
        (const uint16_t*)qh, (const uint16_t*)ql,
        (const uint16_t*)kh, (const uint16_t*)kl, nullptr,
        s, nullptr, nullptr, SEQ, DIM,
        (size_t)SEQ * DIM, (size_t)SEQ * DIM, (size_t)SEQ * SEQ);

    // 5) softmax -> P fp16
    softmax_f16<<<MTOT / 8, 256>>>(s, p16);

    // 6) out = P @ V^T per batch  (fp16, P single x V split = 2 products)
    const dim3 go(DIM / 256, SEQ / 128, BATCH);              // (4, 16, 4)
    g_gemm<2, true, 0, false><<<go, blk, SM2>>>(
        (const uint16_t*)p16, nullptr,
        (const uint16_t*)vth, (const uint16_t*)vtl, nullptr,
        out, nullptr, nullptr, DIM, SEQ,
        (size_t)SEQ * SEQ, (size_t)DIM * SEQ, (size_t)SEQ * DIM);
}

// round 14
// speedup vs baseline: 3.3092x; 1.0881x over previous
#include <cuda_runtime.h>
#include <cuda_bf16.h>
#include <cuda_fp16.h>
#include <cstdint>

// Problem shape (fixed per reference): B=4, S=2048, D=1024, fp32.
#define BATCH 4
#define SEQ   2048
#define DIM   1024
#define MTOT  (BATCH * SEQ)          // 8192

// ---------------------------------------------------------------------------
// Scratch (device globals: allocation-guard safe).
// ---------------------------------------------------------------------------
__device__ __nv_bfloat16 g_xh[(size_t)MTOT * DIM], g_xl[(size_t)MTOT * DIM];
__device__ __half        g_x16[(size_t)MTOT * DIM];
__device__ __nv_bfloat16 g_wth[(size_t)2 * DIM * DIM], g_wtl[(size_t)2 * DIM * DIM];
__device__ __half        g_wv16[(size_t)DIM * DIM];
// q and k combined: [0 .. MTOT*DIM) = q, [MTOT*DIM .. 2*MTOT*DIM) = k
__device__ __nv_bfloat16 g_qkh[(size_t)2 * MTOT * DIM], g_qkl[(size_t)2 * MTOT * DIM];
__device__ float         g_v [(size_t)MTOT * DIM];
__device__ __half        g_vth[(size_t)BATCH * DIM * SEQ];
__device__ float         g_s [(size_t)BATCH * SEQ * SEQ];
__device__ __half        g_p16[(size_t)BATCH * SEQ * SEQ];

// ---------------------------------------------------------------------------
// PTX helpers (ldmatrix / mma / cp.async: all valid on plain sm_103 target)
// ---------------------------------------------------------------------------
__device__ __forceinline__ uint32_t smem_u32(const void* p) {
    return (uint32_t)__cvta_generic_to_shared(p);
}
__device__ __forceinline__ void ldsm_x4(uint32_t* r, uint32_t a) {
    asm volatile("ldmatrix.sync.aligned.m8n8.x4.shared.b16 {%0,%1,%2,%3},[%4];"
                 : "=r"(r[0]), "=r"(r[1]), "=r"(r[2]), "=r"(r[3]) : "r"(a));
}
template<bool F16>
__device__ __forceinline__ void mma_any(float* c, const uint32_t* a,
                                        uint32_t b0, uint32_t b1) {
    if (F16)
        asm volatile(
            "mma.sync.aligned.m16n8k16.row.col.f32.f16.f16.f32 "
            "{%0,%1,%2,%3},{%4,%5,%6,%7},{%8,%9},{%0,%1,%2,%3};"
            : "+f"(c[0]), "+f"(c[1]), "+f"(c[2]), "+f"(c[3])
            : "r"(a[0]), "r"(a[1]), "r"(a[2]), "r"(a[3]), "r"(b0), "r"(b1));
    else
        asm volatile(
            "mma.sync.aligned.m16n8k16.row.col.f32.bf16.bf16.f32 "
            "{%0,%1,%2,%3},{%4,%5,%6,%7},{%8,%9},{%0,%1,%2,%3};"
            : "+f"(c[0]), "+f"(c[1]), "+f"(c[2]), "+f"(c[3])
            : "r"(a[0]), "r"(a[1]), "r"(a[2]), "r"(a[3]), "r"(b0), "r"(b1));
}
__device__ __forceinline__ void cpa16(uint32_t dst, const void* src) {
    asm volatile("cp.async.cg.shared.global [%0], [%1], 16;" :: "r"(dst), "l"(src));
}
__device__ __forceinline__ void cpa_commit() {
    asm volatile("cp.async.commit_group;" ::: "memory");
}
template<int N>
__device__ __forceinline__ void cpa_wait() {
    asm volatile("cp.async.wait_group %0;" :: "n"(N) : "memory");
}

// fp32 pair -> (hi, lo) bf16x2 packed words.  x = hi + lo + O(2^-17 |x|)
__device__ __forceinline__ void split_pack(float x, float y, uint32_t& hi, uint32_t& lo) {
    __nv_bfloat16 hx = __float2bfloat16(x);
    __nv_bfloat16 hy = __float2bfloat16(y);
    __nv_bfloat162 h2; h2.x = hx; h2.y = hy;
    __nv_bfloat162 l2;
    l2.x = __float2bfloat16(x - __bfloat162float(hx));
    l2.y = __float2bfloat16(y - __bfloat162float(hy));
    hi = *reinterpret_cast<uint32_t*>(&h2);
    lo = *reinterpret_cast<uint32_t*>(&l2);
}

// ---------------------------------------------------------------------------
// Generic split HMMA GEMM.  C[M,N] = A @ B^T (+bias), fp32 accum.
//   PROD=3: A=(A0+A1), B=(B0+B1), 3 cross products (bf16 "fp32-like").
//   PROD=1: A=A0, B=B0 single product (fp16 value path).
// Tunables: BN = CTA n-tile (128 or 256); NTH = threads (256 or 512).
//   CTA m-tile fixed 128; warps = NTH/32, layout 4(m) x (BN/64)(n), warp 32x64.
// K-chunk 32, 3-stage cp.async ring.
// OUT=0: fp32 C (+bias).  OUT=1: split bf16 -> Ch, Cl (+bias).
// blockIdx.z: batch index or merged-GEMM selector (strides sA/sB/sC; bias
// selected between bias0 (z==0) and bias1 (z!=0)).
// ---------------------------------------------------------------------------
constexpr int LDROW = 80;                     // bytes/row: 32 elems + 8 pad

// NOTE: __host__ __device__ — harness nvcc lacks --expt-relaxed-constexpr.
__host__ __device__ constexpr int stage_bytes(int prod, int bn) {
    return (((prod == 3) ? 2 : 1) * 128 + ((prod == 1) ? 1 : 2) * bn) * LDROW;
}

template<int PROD, bool F16, int OUT, bool BIAS, int BN, int NTH>
__global__ __launch_bounds__(NTH)
void g_gemm(const uint16_t* __restrict__ A0, const uint16_t* __restrict__ A1,
            const uint16_t* __restrict__ B0, const uint16_t* __restrict__ B1,
            const float* __restrict__ bias0, const float* __restrict__ bias1,
            float* __restrict__ C,
            __nv_bfloat16* __restrict__ Ch, __nv_bfloat16* __restrict__ Cl,
            int N, int K, size_t sA, size_t sB, size_t sC)
{
    constexpr int NA    = (PROD == 3) ? 2 : 1;
    constexpr int NB    = (PROD == 1) ? 1 : 2;
    constexpr int NBBLK = BN / 128;               // B tile in 128-row blocks
    constexpr int OFF_A0 = 0;
    constexpr int OFF_A1 = 128 * LDROW;
    constexpr int OFF_B0 = NA * 128 * LDROW;
    constexpr int OFF_B1 = OFF_B0 + BN * LDROW;
    constexpr int STAGE  = stage_bytes(PROD, BN);
    constexpr int RPT    = 128 / (NTH / 4);       // producer rows per thread

    extern __shared__ char sm[];
    const uint32_t sbase = smem_u32(sm);
    const int tid  = threadIdx.x;
    const int lane = tid & 31;
    const int warp = tid >> 5;
    const int brow = blockIdx.y * 128;
    const int bcol = blockIdx.x * BN;
    const size_t bz = blockIdx.z;
    const int mw = (warp & 3) * 32;
    const int nw = (warp >> 2) * 64;

    // ---- producer constants ----
    const int rr = tid >> 2;                      // 0..NTH/4-1
    const int c8 = tid & 3;                       // 16B chunk within 64B span
    const uint16_t* gA0 = A0 + bz * sA + (size_t)brow * K;
    const uint16_t* gA1 = (NA == 2) ? A1 + bz * sA + (size_t)brow * K : nullptr;
    const uint16_t* gB0 = B0 + bz * sB + (size_t)bcol * K;
    const uint16_t* gB1 = (NB == 2) ? B1 + bz * sB + (size_t)bcol * K : nullptr;

    auto produce = [&](uint32_t sb, int k0) {
        #pragma unroll
        for (int j = 0; j < RPT; j++) {
            const int r = rr + j * (NTH / 4);
            const uint32_t so = (uint32_t)r * LDROW + c8 * 16;
            const size_t   go = (size_t)r * K + k0 + c8 * 8;
            cpa16(sb + OFF_A0 + so, gA0 + go);
            if (NA == 2) cpa16(sb + OFF_A1 + so, gA1 + go);
            #pragma unroll
            for (int bb = 0; bb < NBBLK; bb++) {
                const size_t   gb  = go + (size_t)bb * 128 * K;
                const uint32_t sbb = so + bb * 128 * LDROW;
                cpa16(sb + OFF_B0 + sbb, gB0 + gb);
                if (NB == 2) cpa16(sb + OFF_B1 + sbb, gB1 + gb);
            }
        }
    };

    float acc[2][8][4] = {};

    // ---- prologue: stages 0 and 1 ----
    #pragma unroll
    for (int p = 0; p < 2; p++) {
        produce(sbase + p * STAGE, p * 32);
        cpa_commit();
    }

    // ---- consumer lane constants ----
    const int r8      = lane & 7;
    const int aRowOff = r8 + ((lane >> 3) & 1) * 8;
    const int aColOff = ((lane >> 4) & 1) * 8;
    const int bRowOff = r8 + ((lane >> 4) & 1) * 8;
    const int bColOff = ((lane >> 3) & 1) * 8;

    const int nt = K / 32;
    for (int t = 0; t < nt; t++) {
        cpa_wait<1>();
        __syncthreads();
        const uint32_t sb = sbase + (t % 3) * STAGE;

        #pragma unroll
        for (int ks = 0; ks < 32; ks += 16) {
            uint32_t a0[2][4], a1[2][4];
            #pragma unroll
            for (int i = 0; i < 2; i++) {
                const uint32_t ao = (uint32_t)(mw + i * 16 + aRowOff) * LDROW
                                  + (ks + aColOff) * 2;
                ldsm_x4(a0[i], sb + OFF_A0 + ao);
                if (NA == 2) ldsm_x4(a1[i], sb + OFF_A1 + ao);
            }
            #pragma unroll
            for (int jp = 0; jp < 4; jp++) {
                uint32_t b0[4], b1[4];
                const uint32_t bo = (uint32_t)(nw + jp * 16 + bRowOff) * LDROW
                                  + (ks + bColOff) * 2;
                ldsm_x4(b0, sb + OFF_B0 + bo);
                if (NB == 2) ldsm_x4(b1, sb + OFF_B1 + bo);
                #pragma unroll
                for (int i = 0; i < 2; i++) {
                    mma_any<F16>(acc[i][2 * jp],     a0[i], b0[0], b0[1]);
                    mma_any<F16>(acc[i][2 * jp + 1], a0[i], b0[2], b0[3]);
                    if (NB == 2) {
                        mma_any<F16>(acc[i][2 * jp],     a0[i], b1[0], b1[1]);
                        mma_any<F16>(acc[i][2 * jp + 1], a0[i], b1[2], b1[3]);
                    }
                    if (NA == 2) {
                        mma_any<F16>(acc[i][2 * jp],     a1[i], b0[0], b0[1]);
                        mma_any<F16>(acc[i][2 * jp + 1], a1[i], b0[2], b0[3]);
                    }
                }
            }
        }

        // stage (t+2)%3 was last consumed at iter t-1; the barrier above makes
        // this refill WAR-safe.
        if (t + 2 < nt)
            produce(sbase + ((t + 2) % 3) * STAGE, (t + 2) * 32);
        cpa_commit();   // always commit: uniform wait_group accounting
    }

    // ---- epilogue ----
    const float* bp = BIAS ? ((bz == 0) ? bias0 : bias1) : nullptr;
    const int g  = lane >> 2;
    const int tg = lane & 3;
    #pragma unroll
    for (int i = 0; i < 2; i++) {
        #pragma unroll
        for (int j = 0; j < 8; j++) {
            const int m = brow + mw + i * 16 + g;
            const int n = bcol + nw + j * 8 + tg * 2;
            float b0 = 0.f, b1 = 0.f;
            if (BIAS) { b0 = bp[n]; b1 = bp[n + 1]; }
            const float v00 = acc[i][j][0] + b0, v01 = acc[i][j][1] + b1;
            const float v10 = acc[i][j][2] + b0, v11 = acc[i][j][3] + b1;
            if (OUT == 0) {
                float* Cp = C + bz * sC;
                *(float2*)&Cp[(size_t)m * N + n]       = make_float2(v00, v01);
                *(float2*)&Cp[(size_t)(m + 8) * N + n] = make_float2(v10, v11);
            } else {
                uint32_t h0, l0, h1, l1;
                split_pack(v00, v01, h0, l0);
                split_pack(v10, v11, h1, l1);
                __nv_bfloat16* Chp = Ch + bz * sC;
                __nv_bfloat16* Clp = Cl + bz * sC;
                *(uint32_t*)&Chp[(size_t)m * N + n]       = h0;
                *(uint32_t*)&Clp[(size_t)m * N + n]       = l0;
                *(uint32_t*)&Chp[(size_t)(m + 8) * N + n] = h1;
                *(uint32_t*)&Clp[(size_t)(m + 8) * N + n] = l1;
            }
        }
    }
}

// ---------------------------------------------------------------------------
// convert_x: fp32 -> bf16 hi/lo split AND fp16 single, one pass over x.
// ---------------------------------------------------------------------------
__global__ __launch_bounds__(256)
void convert_x(const float4* __restrict__ X, uint32_t* __restrict__ Xh,
               uint32_t* __restrict__ Xl, uint32_t* __restrict__ X16)
{
    const size_t i = (size_t)blockIdx.x * 256 + threadIdx.x;
    float4 v = X[i];
    uint32_t h0, l0, h1, l1;
    split_pack(v.x, v.y, h0, l0);
    split_pack(v.z, v.w, h1, l1);
    Xh[2 * i] = h0; Xh[2 * i + 1] = h1;
    Xl[2 * i] = l0; Xl[2 * i + 1] = l1;
    __half2 p0 = __floats2half2_rn(v.x, v.y);
    __half2 p1 = __floats2half2_rn(v.z, v.w);
    X16[2 * i]     = *reinterpret_cast<uint32_t*>(&p0);
    X16[2 * i + 1] = *reinterpret_cast<uint32_t*>(&p1);
}

// ---------------------------------------------------------------------------
// convert_wt: W [in,out] fp32 -> Wt [out,in] bf16 hi/lo (transpose + split).
// ---------------------------------------------------------------------------
__global__ __launch_bounds__(256)
void convert_wt(const float* __restrict__ W, __nv_bfloat16* __restrict__ Th,
                __nv_bfloat16* __restrict__ Tl)
{
    __shared__ float t[32][33];
    const int bx = blockIdx.x * 32, by = blockIdx.y * 32;
    const int x = threadIdx.x, y = threadIdx.y;
    #pragma unroll
    for (int r = 0; r < 4; r++)
        t[y + 8 * r][x] = W[(size_t)(by + y + 8 * r) * DIM + bx + x];
    __syncthreads();
    #pragma unroll
    for (int r = 0; r < 4; r++) {
        float v = t[x][y + 8 * r];
        __nv_bfloat16 h = __float2bfloat16(v);
        __nv_bfloat16 l = __float2bfloat16(v - __bfloat162float(h));
        const size_t o = (size_t)(bx + y + 8 * r) * DIM + by + x;
        Th[o] = h; Tl[o] = l;
    }
}

// convert_wt_f16: W [in,out] fp32 -> Wt [out,in] fp16 single.
__global__ __launch_bounds__(256)
void convert_wt_f16(const float* __restrict__ W, __half* __restrict__ T)
{
    __shared__ float t[32][33];
    const int bx = blockIdx.x * 32, by = blockIdx.y * 32;
    const int x = threadIdx.x, y = threadIdx.y;
    #pragma unroll
    for (int r = 0; r < 4; r++)
        t[y + 8 * r][x] = W[(size_t)(by + y + 8 * r) * DIM + bx + x];
    __syncthreads();
    #pragma unroll
    for (int r = 0; r < 4; r++)
        T[(size_t)(bx + y + 8 * r) * DIM + by + x] = __float2half(t[x][y + 8 * r]);
}

// ---------------------------------------------------------------------------
// transpose_v: v [b,2048,1024] fp32 -> vt fp16 [b,1024,2048] (hi only).
// ---------------------------------------------------------------------------
__global__ __launch_bounds__(256)
void transpose_v(const float* __restrict__ V, __half* __restrict__ Th)
{
    __shared__ float t[32][33];
    const int bx = blockIdx.x * 32;          // s
    const int by = blockIdx.y * 32;          // d
    const size_t bofI = (size_t)blockIdx.z * SEQ * DIM;
    const size_t bofO = (size_t)blockIdx.z * DIM * SEQ;
    const int x = threadIdx.x, y = threadIdx.y;
    #pragma unroll
    for (int r = 0; r < 4; r++)
        t[y + 8 * r][x] = V[bofI + (size_t)(bx + y + 8 * r) * DIM + by + x];
    __syncthreads();
    #pragma unroll
    for (int r = 0; r < 4; r++)
        Th[bofO + (size_t)(by + y + 8 * r) * SEQ + bx + x] =
            __float2half(t[x][y + 8 * r]);
}

// ---------------------------------------------------------------------------
// Row softmax, length 2048, one warp per row; outputs single fp16 P.
// ---------------------------------------------------------------------------
__global__ __launch_bounds__(256)
void softmax_f16(const float* __restrict__ S, __half* __restrict__ P)
{
    const int lane = threadIdx.x & 31;
    const int w    = threadIdx.x >> 5;
    const size_t row = (size_t)blockIdx.x * 8 + w;
    const float4* p = reinterpret_cast<const float4*>(S + row * 2048);

    float4 v[16];
    #pragma unroll
    for (int i = 0; i < 16; i++) v[i] = p[lane + 32 * i];

    float m = -3.0e38f;
    #pragma unroll
    for (int i = 0; i < 16; i++)
        m = fmaxf(m, fmaxf(fmaxf(v[i].x, v[i].y), fmaxf(v[i].z, v[i].w)));
    #pragma unroll
    for (int o = 16; o; o >>= 1) m = fmaxf(m, __shfl_xor_sync(0xffffffffu, m, o));

    float s = 0.f;
    #pragma unroll
    for (int i = 0; i < 16; i++) {
        v[i].x = __expf(v[i].x - m); v[i].y = __expf(v[i].y - m);
        v[i].z = __expf(v[i].z - m); v[i].w = __expf(v[i].w - m);
        s += v[i].x + v[i].y + v[i].z + v[i].w;
    }
    #pragma unroll
    for (int o = 16; o; o >>= 1) s += __shfl_xor_sync(0xffffffffu, s, o);

    const float inv = 1.0f / s;
    uint32_t* op = reinterpret_cast<uint32_t*>(P) + row * 1024;
    #pragma unroll
    for (int i = 0; i < 16; i++) {
        __half2 p0 = __floats2half2_rn(v[i].x * inv, v[i].y * inv);
        __half2 p1 = __floats2half2_rn(v[i].z * inv, v[i].w * inv);
        const int c = lane + 32 * i;
        op[2 * c]     = *reinterpret_cast<uint32_t*>(&p0);
        op[2 * c + 1] = *reinterpret_cast<uint32_t*>(&p1);
    }
}

// ---------------------------------------------------------------------------
// Launch sequence.
// Inputs (metadata order): x, Wq, bq, Wk, bk, Wv, bv.  Output: [B,S,D] fp32.
// ---------------------------------------------------------------------------
extern "C" void kernel_launch(void* const* d_in, const int* in_sizes, int n_in,
                              void* d_out, int out_size)
{
    const float* x  = (const float*)d_in[0];
    const float* Wq = (const float*)d_in[1];
    const float* bq = (const float*)d_in[2];
    const float* Wk = (const float*)d_in[3];
    const float* bk = (const float*)d_in[4];
    const float* Wv = (const float*)d_in[5];
    const float* bv = (const float*)d_in[6];
    float* out = (float*)d_out;

    __nv_bfloat16 *xh, *xl, *wth, *wtl, *qkh, *qkl;
    __half *x16, *wv16, *vth, *p16;
    float *v, *s;
    cudaGetSymbolAddress((void**)&xh,   g_xh);  cudaGetSymbolAddress((void**)&xl,  g_xl);
    cudaGetSymbolAddress((void**)&x16,  g_x16);
    cudaGetSymbolAddress((void**)&wth,  g_wth); cudaGetSymbolAddress((void**)&wtl, g_wtl);
    cudaGetSymbolAddress((void**)&wv16, g_wv16);
    cudaGetSymbolAddress((void**)&qkh,  g_qkh); cudaGetSymbolAddress((void**)&qkl, g_qkl);
    cudaGetSymbolAddress((void**)&v,    g_v);
    cudaGetSymbolAddress((void**)&vth,  g_vth);
    cudaGetSymbolAddress((void**)&s,    g_s);
    cudaGetSymbolAddress((void**)&p16,  g_p16);

    // smem: 3 stages, derived from the same stage_bytes() the kernel uses.
    const int SM_P3_128 = 3 * stage_bytes(3, 128);   // 122880 -> 1 CTA/SM
    const int SM_P1_256 = 3 * stage_bytes(1, 256);   //  92160 -> 2 CTA/SM

    cudaFuncSetAttribute(g_gemm<3, false, 1, true,  128, 256>,
                         cudaFuncAttributeMaxDynamicSharedMemorySize, SM_P3_128);
    cudaFuncSetAttribute(g_gemm<3, false, 0, false, 128, 256>,
                         cudaFuncAttributeMaxDynamicSharedMemorySize, SM_P3_128);
    cudaFuncSetAttribute(g_gemm<1, true,  0, true,  256, 512>,
                         cudaFuncAttributeMaxDynamicSharedMemorySize, SM_P1_256);
    cudaFuncSetAttribute(g_gemm<1, true,  0, false, 256, 512>,
                         cudaFuncAttributeMaxDynamicSharedMemorySize, SM_P1_256);

    const size_t WOFF = (size_t)DIM * DIM;
    const size_t QKO  = (size_t)MTOT * DIM;          // k offset in g_qk*
    const dim3 bwt(32, 8);
    const dim3 gwt(DIM / 32, DIM / 32);

    // 1) conversions
    convert_x<<<(MTOT * DIM) / (256 * 4), 256>>>((const float4*)x,
        (uint32_t*)xh, (uint32_t*)xl, (uint32_t*)x16);
    convert_wt<<<gwt, bwt>>>(Wq, wth,        wtl);
    convert_wt<<<gwt, bwt>>>(Wk, wth + WOFF, wtl + WOFF);
    convert_wt_f16<<<gwt, bwt>>>(Wv, wv16);

    // 2) merged Q+K projection: z selects weights/bias/output slice.
    //    1024 CTAs -> 6.92 waves @148 SMs (1.2% tail vs 13.5% before).
    const dim3 gqk(DIM / 128, MTOT / 128, 2);        // (8, 64, 2)
    g_gemm<3, false, 1, true, 128, 256><<<gqk, 256, SM_P3_128>>>(
        (const uint16_t*)xh, (const uint16_t*)xl,
        (const uint16_t*)wth, (const uint16_t*)wtl, bq, bk,
        nullptr, qkh, qkl, DIM, DIM, 0, WOFF, QKO);

    //    V projection: 1-product fp16, 256 CTAs @ 2 CTA/SM = single wave.
    const dim3 gv(DIM / 256, MTOT / 128, 1);         // (4, 64)
    g_gemm<1, true, 0, true, 256, 512><<<gv, 512, SM_P1_256>>>(
        (const uint16_t*)x16, nullptr,
        (const uint16_t*)wv16, nullptr, bv, bv,
        v, nullptr, nullptr, DIM, DIM, 0, 0, 0);

    // 3) V transpose -> fp16 [b, d, s]
    transpose_v<<<dim3(SEQ / 32, DIM / 32, BATCH), bwt>>>(v, vth);

    // 4) scores = Q @ K^T per batch -> fp32 S  (bf16 3-product, 1024 CTAs)
    const dim3 gs(SEQ / 128, SEQ / 128, BATCH);      // (16, 16, 4)
    g_gemm<3, false, 0, false, 128, 256><<<gs, 256, SM_P3_128>>>(
        (const uint16_t*)qkh, (const uint16_t*)qkl,
        (const uint16_t*)(qkh + QKO), (const uint16_t*)(qkl + QKO),
        nullptr, nullptr,
        s, nullptr, nullptr, SEQ, DIM,
        (size_t)SEQ * DIM, (size_t)SEQ * DIM, (size_t)SEQ * SEQ);

    // 5) softmax -> P fp16
    softmax_f16<<<MTOT / 8, 256>>>(s, p16);

    // 6) out = P @ V^T per batch (fp16 single product, 256 CTAs, one wave)
    const dim3 go(DIM / 256, SEQ / 128, BATCH);      // (4, 16, 4)
    g_gemm<1, true, 0, false, 256, 512><<<go, 512, SM_P1_256>>>(
        (const uint16_t*)p16, nullptr,
        (const uint16_t*)vth, nullptr, nullptr, nullptr,
        out, nullptr, nullptr, DIM, SEQ,
        (size_t)SEQ * SEQ, (size_t)DIM * SEQ, (size_t)SEQ * DIM);
}

// round 15
// speedup vs baseline: 3.7149x; 1.1226x over previous
#include <cuda_runtime.h>
#include <cuda_bf16.h>
#include <cuda_fp16.h>
#include <cstdint>

// Problem shape (fixed per reference): B=4, S=2048, D=1024, fp32.
#define BATCH 4
#define SEQ   2048
#define DIM   1024
#define MTOT  (BATCH * SEQ)          // 8192

// ---------------------------------------------------------------------------
// Scratch (device globals: allocation-guard safe).
// ---------------------------------------------------------------------------
__device__ __nv_bfloat16 g_xh[(size_t)MTOT * DIM], g_xl[(size_t)MTOT * DIM];
__device__ __half        g_x16[(size_t)MTOT * DIM];
__device__ __nv_bfloat16 g_wth[(size_t)2 * DIM * DIM], g_wtl[(size_t)2 * DIM * DIM];
__device__ __half        g_wv16[(size_t)DIM * DIM];        // [in(k), out(n)] natural
// q and k combined: [0 .. MTOT*DIM) = q, [MTOT*DIM ..) = k
__device__ __nv_bfloat16 g_qkh[(size_t)2 * MTOT * DIM], g_qkl[(size_t)2 * MTOT * DIM];
__device__ __half        g_v16[(size_t)MTOT * DIM];        // [s, d] natural
__device__ float         g_s [(size_t)BATCH * SEQ * SEQ];
__device__ __half        g_p16[(size_t)BATCH * SEQ * SEQ];

// ---------------------------------------------------------------------------
// PTX helpers (ldmatrix / mma / cp.async: all valid on plain sm_103 target)
// ---------------------------------------------------------------------------
__device__ __forceinline__ uint32_t smem_u32(const void* p) {
    return (uint32_t)__cvta_generic_to_shared(p);
}
__device__ __forceinline__ void ldsm_x4(uint32_t* r, uint32_t a) {
    asm volatile("ldmatrix.sync.aligned.m8n8.x4.shared.b16 {%0,%1,%2,%3},[%4];"
                 : "=r"(r[0]), "=r"(r[1]), "=r"(r[2]), "=r"(r[3]) : "r"(a));
}
__device__ __forceinline__ void ldsm_x4_t(uint32_t* r, uint32_t a) {
    asm volatile("ldmatrix.sync.aligned.m8n8.x4.trans.shared.b16 {%0,%1,%2,%3},[%4];"
                 : "=r"(r[0]), "=r"(r[1]), "=r"(r[2]), "=r"(r[3]) : "r"(a));
}
template<bool F16>
__device__ __forceinline__ void mma_any(float* c, const uint32_t* a,
                                        uint32_t b0, uint32_t b1) {
    if (F16)
        asm volatile(
            "mma.sync.aligned.m16n8k16.row.col.f32.f16.f16.f32 "
            "{%0,%1,%2,%3},{%4,%5,%6,%7},{%8,%9},{%0,%1,%2,%3};"
            : "+f"(c[0]), "+f"(c[1]), "+f"(c[2]), "+f"(c[3])
            : "r"(a[0]), "r"(a[1]), "r"(a[2]), "r"(a[3]), "r"(b0), "r"(b1));
    else
        asm volatile(
            "mma.sync.aligned.m16n8k16.row.col.f32.bf16.bf16.f32 "
            "{%0,%1,%2,%3},{%4,%5,%6,%7},{%8,%9},{%0,%1,%2,%3};"
            : "+f"(c[0]), "+f"(c[1]), "+f"(c[2]), "+f"(c[3])
            : "r"(a[0]), "r"(a[1]), "r"(a[2]), "r"(a[3]), "r"(b0), "r"(b1));
}
__device__ __forceinline__ void cpa16(uint32_t dst, const void* src) {
    asm volatile("cp.async.cg.shared.global [%0], [%1], 16;" :: "r"(dst), "l"(src));
}
__device__ __forceinline__ void cpa_commit() {
    asm volatile("cp.async.commit_group;" ::: "memory");
}
template<int N>
__device__ __forceinline__ void cpa_wait() {
    asm volatile("cp.async.wait_group %0;" :: "n"(N) : "memory");
}

// fp32 pair -> (hi, lo) bf16x2 packed words.  x = hi + lo + O(2^-17 |x|)
__device__ __forceinline__ void split_pack(float x, float y, uint32_t& hi, uint32_t& lo) {
    __nv_bfloat16 hx = __float2bfloat16(x);
    __nv_bfloat16 hy = __float2bfloat16(y);
    __nv_bfloat162 h2; h2.x = hx; h2.y = hy;
    __nv_bfloat162 l2;
    l2.x = __float2bfloat16(x - __bfloat162float(hx));
    l2.y = __float2bfloat16(y - __bfloat162float(hy));
    hi = *reinterpret_cast<uint32_t*>(&h2);
    lo = *reinterpret_cast<uint32_t*>(&l2);
}

// ---------------------------------------------------------------------------
// Generic split HMMA GEMM.  C[M,N] = A @ op(B) (+bias), fp32 accum.
//   PROD=3: A=(A0+A1), B=(B0+B1) K-major, 3 cross products (bf16 fp32-like).
//   PROD=1: single product (fp16 value path).
//   BT=false: B stored [N,K] row-major (op = B^T via K-major ldsm).
//   BT=true : B stored [K,N] row-major natural; ldmatrix.trans (PROD=1 only).
// CTA tile 128x128, 256 threads = 8 warps (4m x 2n), warp 32x64, K-chunk 32.
// NST-stage cp.async ring (2 for PROD=3 -> 2 CTA/SM; 3 for PROD=1).
// OUT=0: fp32 (+bias). OUT=1: split bf16 Ch/Cl (+bias). OUT=2: fp16 (+bias).
// blockIdx.z: batch / merged-GEMM selector via sA/sB/sC; bias0 (z==0)/bias1.
// ---------------------------------------------------------------------------
constexpr int LDROW = 80;                     // K-major row: 32 elems + 8 pad

// NOTE: __host__ __device__ — harness nvcc lacks --expt-relaxed-constexpr.
__host__ __device__ constexpr int stage_bytes(int prod, bool bt) {
    return (((prod == 3) ? 2 : 1) * 128) * LDROW
         + (bt ? 32 * (128 + 8) * 2 : ((prod == 3) ? 2 : 1) * 128 * LDROW);
}

template<int PROD, bool F16, int OUT, bool BIAS, int NST, bool BT>
__global__ __launch_bounds__(256, 2)
void g_gemm(const uint16_t* __restrict__ A0, const uint16_t* __restrict__ A1,
            const uint16_t* __restrict__ B0, const uint16_t* __restrict__ B1,
            const float* __restrict__ bias0, const float* __restrict__ bias1,
            float* __restrict__ C,
            __nv_bfloat16* __restrict__ Ch, __nv_bfloat16* __restrict__ Cl,
            int N, int K, size_t sA, size_t sB, size_t sC)
{
    constexpr int NA     = (PROD == 3) ? 2 : 1;
    constexpr int NB     = (PROD == 3) ? 2 : 1;
    constexpr int OFF_A0 = 0;
    constexpr int OFF_A1 = 128 * LDROW;
    constexpr int OFF_B0 = NA * 128 * LDROW;
    constexpr int OFF_B1 = OFF_B0 + 128 * LDROW;       // only when NB==2 (!BT)
    constexpr int LDBT   = 128 + 8;                    // BT row in elems
    constexpr int STAGE  = stage_bytes(PROD, BT);

    extern __shared__ char sm[];
    const uint32_t sbase = smem_u32(sm);
    const int tid  = threadIdx.x;
    const int lane = tid & 31;
    const int warp = tid >> 5;
    const int brow = blockIdx.y * 128;
    const int bcol = blockIdx.x * 128;
    const size_t bz = blockIdx.z;
    const int mw = (warp & 3) * 32;
    const int nw = (warp >> 2) * 64;

    // ---- producer constants ----
    const int rr = tid >> 2;                      // 0..63 (K-major rows)
    const int c8 = tid & 3;                       // 16B chunk in 64B span
    const uint16_t* gA0 = A0 + bz * sA + (size_t)brow * K;
    const uint16_t* gA1 = (NA == 2) ? A1 + bz * sA + (size_t)brow * K : nullptr;
    const uint16_t* gB0 = BT ? B0 + bz * sB + bcol
                             : B0 + bz * sB + (size_t)bcol * K;
    const uint16_t* gB1 = (NB == 2) ? B1 + bz * sB + (size_t)bcol * K : nullptr;

    auto produce = [&](uint32_t sb, int k0) {
        #pragma unroll
        for (int j = 0; j < 2; j++) {             // 2 rows per thread
            const int r = rr + j * 64;
            const uint32_t so = (uint32_t)r * LDROW + c8 * 16;
            const size_t   go = (size_t)r * K + k0 + c8 * 8;
            cpa16(sb + OFF_A0 + so, gA0 + go);
            if (NA == 2) cpa16(sb + OFF_A1 + so, gA1 + go);
            if (!BT) {
                cpa16(sb + OFF_B0 + so, gB0 + go);
                if (NB == 2) cpa16(sb + OFF_B1 + so, gB1 + go);
            }
        }
        if (BT) {
            // 32 k-rows x 128 n-elems, natural [K,N] source rows
            const int krow = tid >> 3;            // 0..31
            const int cc   = tid & 7;
            #pragma unroll
            for (int j = 0; j < 2; j++) {
                const int c = cc + j * 8;         // 0..15
                cpa16(sb + OFF_B0 + (uint32_t)krow * LDBT * 2 + c * 16,
                      gB0 + (size_t)(k0 + krow) * N + c * 8);
            }
        }
    };

    float acc[2][8][4] = {};

    // ---- prologue: stages 0 and 1 ----
    produce(sbase, 0);          cpa_commit();
    produce(sbase + STAGE, 32); cpa_commit();

    // ---- consumer lane constants ----
    const int r8      = lane & 7;
    const int aRowOff = r8 + ((lane >> 3) & 1) * 8;
    const int aColOff = ((lane >> 4) & 1) * 8;
    const int bRowOff = r8 + ((lane >> 4) & 1) * 8;   // NT: n-row
    const int bColOff = ((lane >> 3) & 1) * 8;        // NT: k-col
    const int btR     = r8 + ((lane >> 3) & 1) * 8;   // BT: k-row
    const int btC     = (lane >> 4) * 8;              // BT: n-col

    const int nt = K / 32;
    for (int t = 0; t < nt; t++) {
        cpa_wait<1>();
        __syncthreads();
        const uint32_t sb = sbase + (t % NST) * STAGE;

        #pragma unroll
        for (int ks = 0; ks < 32; ks += 16) {
            uint32_t a0[2][4], a1[2][4];
            #pragma unroll
            for (int i = 0; i < 2; i++) {
                const uint32_t ao = (uint32_t)(mw + i * 16 + aRowOff) * LDROW
                                  + (ks + aColOff) * 2;
                ldsm_x4(a0[i], sb + OFF_A0 + ao);
                if (NA == 2) ldsm_x4(a1[i], sb + OFF_A1 + ao);
            }
            #pragma unroll
            for (int jp = 0; jp < 4; jp++) {
                uint32_t b0[4], b1[4];
                if (BT) {
                    const uint32_t bo = (uint32_t)(ks + btR) * LDBT
                                      + nw + jp * 16 + btC;
                    ldsm_x4_t(b0, sb + OFF_B0 + bo * 2);
                } else {
                    const uint32_t bo = (uint32_t)(nw + jp * 16 + bRowOff) * LDROW
                                      + (ks + bColOff) * 2;
                    ldsm_x4(b0, sb + OFF_B0 + bo);
                    if (NB == 2) ldsm_x4(b1, sb + OFF_B1 + bo);
                }
                #pragma unroll
                for (int i = 0; i < 2; i++) {
                    mma_any<F16>(acc[i][2 * jp],     a0[i], b0[0], b0[1]);
                    mma_any<F16>(acc[i][2 * jp + 1], a0[i], b0[2], b0[3]);
                    if (NB == 2) {
                        mma_any<F16>(acc[i][2 * jp],     a0[i], b1[0], b1[1]);
                        mma_any<F16>(acc[i][2 * jp + 1], a0[i], b1[2], b1[3]);
                    }
                    if (NA == 2) {
                        mma_any<F16>(acc[i][2 * jp],     a1[i], b0[0], b0[1]);
                        mma_any<F16>(acc[i][2 * jp + 1], a1[i], b0[2], b0[3]);
                    }
                }
            }
        }

        // NST=3: stage (t+2)%3 was last read at iter t-1; the barrier at the
        // top of THIS iter makes the refill WAR-safe.
        // NST=2: stage (t+2)%2 == t%2 is the one just computed -> need a
        // post-compute barrier before overwriting it.
        if (NST == 2) __syncthreads();
        if (t + 2 < nt)
            produce(sbase + ((t + 2) % NST) * STAGE, (t + 2) * 32);
        cpa_commit();   // always commit: uniform wait_group accounting
    }

    // ---- epilogue ----
    const float* bp = BIAS ? ((bz == 0) ? bias0 : bias1) : nullptr;
    const int g  = lane >> 2;
    const int tg = lane & 3;
    #pragma unroll
    for (int i = 0; i < 2; i++) {
        #pragma unroll
        for (int j = 0; j < 8; j++) {
            const int m = brow + mw + i * 16 + g;
            const int n = bcol + nw + j * 8 + tg * 2;
            float b0 = 0.f, b1 = 0.f;
            if (BIAS) { b0 = bp[n]; b1 = bp[n + 1]; }
            const float v00 = acc[i][j][0] + b0, v01 = acc[i][j][1] + b1;
            const float v10 = acc[i][j][2] + b0, v11 = acc[i][j][3] + b1;
            if (OUT == 0) {
                float* Cp = C + bz * sC;
                *(float2*)&Cp[(size_t)m * N + n]       = make_float2(v00, v01);
                *(float2*)&Cp[(size_t)(m + 8) * N + n] = make_float2(v10, v11);
            } else if (OUT == 1) {
                uint32_t h0, l0, h1, l1;
                split_pack(v00, v01, h0, l0);
                split_pack(v10, v11, h1, l1);
                __nv_bfloat16* Chp = Ch + bz * sC;
                __nv_bfloat16* Clp = Cl + bz * sC;
                *(uint32_t*)&Chp[(size_t)m * N + n]       = h0;
                *(uint32_t*)&Clp[(size_t)m * N + n]       = l0;
                *(uint32_t*)&Chp[(size_t)(m + 8) * N + n] = h1;
                *(uint32_t*)&Clp[(size_t)(m + 8) * N + n] = l1;
            } else {
                __half* Cp = (__half*)C + bz * sC;
                __half2 h0 = __floats2half2_rn(v00, v01);
                __half2 h1 = __floats2half2_rn(v10, v11);
                *(uint32_t*)&Cp[(size_t)m * N + n]       = *(uint32_t*)&h0;
                *(uint32_t*)&Cp[(size_t)(m + 8) * N + n] = *(uint32_t*)&h1;
            }
        }
    }
}

// ---------------------------------------------------------------------------
// convert_x: fp32 -> bf16 hi/lo split AND fp16 single, one pass over x.
// ---------------------------------------------------------------------------
__global__ __launch_bounds__(256)
void convert_x(const float4* __restrict__ X, uint32_t* __restrict__ Xh,
               uint32_t* __restrict__ Xl, uint32_t* __restrict__ X16)
{
    const size_t i = (size_t)blockIdx.x * 256 + threadIdx.x;
    float4 v = X[i];
    uint32_t h0, l0, h1, l1;
    split_pack(v.x, v.y, h0, l0);
    split_pack(v.z, v.w, h1, l1);
    Xh[2 * i] = h0; Xh[2 * i + 1] = h1;
    Xl[2 * i] = l0; Xl[2 * i + 1] = l1;
    __half2 p0 = __floats2half2_rn(v.x, v.y);
    __half2 p1 = __floats2half2_rn(v.z, v.w);
    X16[2 * i]     = *reinterpret_cast<uint32_t*>(&p0);
    X16[2 * i + 1] = *reinterpret_cast<uint32_t*>(&p1);
}

// ---------------------------------------------------------------------------
// convert_w3: one launch for all weights.
//   z=0: Wq -> transpose+split bf16 into Th/Tl[0];  z=1: Wk -> Th/Tl[+WOFF];
//   z=2: Wv -> straight fp32->fp16 (no transpose; BT GEMM consumes [in,out]).
// ---------------------------------------------------------------------------
__global__ __launch_bounds__(256)
void convert_w3(const float* __restrict__ Wq, const float* __restrict__ Wk,
                const float* __restrict__ Wv,
                __nv_bfloat16* __restrict__ Th, __nv_bfloat16* __restrict__ Tl,
                __half* __restrict__ T16)
{
    const int bx = blockIdx.x * 32, by = blockIdx.y * 32;
    const int x = threadIdx.x, y = threadIdx.y;
    const int z = blockIdx.z;
    if (z == 2) {
        #pragma unroll
        for (int r = 0; r < 4; r++) {
            const size_t o = (size_t)(by + y + 8 * r) * DIM + bx + x;
            T16[o] = __float2half(Wv[o]);
        }
        return;
    }
    __shared__ float t[32][33];
    const float* W = (z == 0) ? Wq : Wk;
    const size_t woff = (size_t)z * DIM * DIM;
    #pragma unroll
    for (int r = 0; r < 4; r++)
        t[y + 8 * r][x] = W[(size_t)(by + y + 8 * r) * DIM + bx + x];
    __syncthreads();
    #pragma unroll
    for (int r = 0; r < 4; r++) {
        float v = t[x][y + 8 * r];
        __nv_bfloat16 h = __float2bfloat16(v);
        __nv_bfloat16 l = __float2bfloat16(v - __bfloat162float(h));
        const size_t o = woff + (size_t)(bx + y + 8 * r) * DIM + by + x;
        Th[o] = h; Tl[o] = l;
    }
}

// ---------------------------------------------------------------------------
// Row softmax, length 2048, one warp per row; outputs single fp16 P.
// ---------------------------------------------------------------------------
__global__ __launch_bounds__(256)
void softmax_f16(const float* __restrict__ S, __half* __restrict__ P)
{
    const int lane = threadIdx.x & 31;
    const int w    = threadIdx.x >> 5;
    const size_t row = (size_t)blockIdx.x * 8 + w;
    const float4* p = reinterpret_cast<const float4*>(S + row * 2048);

    float4 v[16];
    #pragma unroll
    for (int i = 0; i < 16; i++) v[i] = p[lane + 32 * i];

    float m = -3.0e38f;
    #pragma unroll
    for (int i = 0; i < 16; i++)
        m = fmaxf(m, fmaxf(fmaxf(v[i].x, v[i].y), fmaxf(v[i].z, v[i].w)));
    #pragma unroll
    for (int o = 16; o; o >>= 1) m = fmaxf(m, __shfl_xor_sync(0xffffffffu, m, o));

    float s = 0.f;
    #pragma unroll
    for (int i = 0; i < 16; i++) {
        v[i].x = __expf(v[i].x - m); v[i].y = __expf(v[i].y - m);
        v[i].z = __expf(v[i].z - m); v[i].w = __expf(v[i].w - m);
        s += v[i].x + v[i].y + v[i].z + v[i].w;
    }
    #pragma unroll
    for (int o = 16; o; o >>= 1) s += __shfl_xor_sync(0xffffffffu, s, o);

    const float inv = 1.0f / s;
    uint32_t* op = reinterpret_cast<uint32_t*>(P) + row * 1024;
    #pragma unroll
    for (int i = 0; i < 16; i++) {
        __half2 p0 = __floats2half2_rn(v[i].x * inv, v[i].y * inv);
        __half2 p1 = __floats2half2_rn(v[i].z * inv, v[i].w * inv);
        const int c = lane + 32 * i;
        op[2 * c]     = *reinterpret_cast<uint32_t*>(&p0);
        op[2 * c + 1] = *reinterpret_cast<uint32_t*>(&p1);
    }
}

// ---------------------------------------------------------------------------
// Launch sequence.
// Inputs (metadata order): x, Wq, bq, Wk, bk, Wv, bv.  Output: [B,S,D] fp32.
// ---------------------------------------------------------------------------
extern "C" void kernel_launch(void* const* d_in, const int* in_sizes, int n_in,
                              void* d_out, int out_size)
{
    const float* x  = (const float*)d_in[0];
    const float* Wq = (const float*)d_in[1];
    const float* bq = (const float*)d_in[2];
    const float* Wk = (const float*)d_in[3];
    const float* bk = (const float*)d_in[4];
    const float* Wv = (const float*)d_in[5];
    const float* bv = (const float*)d_in[6];
    float* out = (float*)d_out;

    __nv_bfloat16 *xh, *xl, *wth, *wtl, *qkh, *qkl;
    __half *x16, *wv16, *v16, *p16;
    float *s;
    cudaGetSymbolAddress((void**)&xh,   g_xh);  cudaGetSymbolAddress((void**)&xl,  g_xl);
    cudaGetSymbolAddress((void**)&x16,  g_x16);
    cudaGetSymbolAddress((void**)&wth,  g_wth); cudaGetSymbolAddress((void**)&wtl, g_wtl);
    cudaGetSymbolAddress((void**)&wv16, g_wv16);
    cudaGetSymbolAddress((void**)&qkh,  g_qkh); cudaGetSymbolAddress((void**)&qkl, g_qkl);
    cudaGetSymbolAddress((void**)&v16,  g_v16);
    cudaGetSymbolAddress((void**)&s,    g_s);
    cudaGetSymbolAddress((void**)&p16,  g_p16);

    // smem: derived from the SAME stage_bytes() the kernel uses.
    const int SM_P3 = 2 * stage_bytes(3, false);   // 2 x 40960 = 81920 (2-stage)
    const int SM_BT = 3 * stage_bytes(1, true);    // 3 x 18944 = 56832

    cudaFuncSetAttribute(g_gemm<3, false, 1, true,  2, false>,
                         cudaFuncAttributeMaxDynamicSharedMemorySize, SM_P3);
    cudaFuncSetAttribute(g_gemm<3, false, 0, false, 2, false>,
                         cudaFuncAttributeMaxDynamicSharedMemorySize, SM_P3);
    cudaFuncSetAttribute(g_gemm<1, true,  2, true,  3, true>,
                         cudaFuncAttributeMaxDynamicSharedMemorySize, SM_BT);
    cudaFuncSetAttribute(g_gemm<1, true,  0, false, 3, true>,
                         cudaFuncAttributeMaxDynamicSharedMemorySize, SM_BT);

    const size_t WOFF = (size_t)DIM * DIM;
    const size_t QKO  = (size_t)MTOT * DIM;          // k offset in g_qk*

    // 1) conversions (2 launches total)
    convert_x<<<(MTOT * DIM) / (256 * 4), 256>>>((const float4*)x,
        (uint32_t*)xh, (uint32_t*)xl, (uint32_t*)x16);
    convert_w3<<<dim3(DIM / 32, DIM / 32, 3), dim3(32, 8)>>>(
        Wq, Wk, Wv, wth, wtl, wv16);

    // 2) merged Q+K projection (bf16 3-product, 2-stage, 2 CTA/SM)
    const dim3 gqk(DIM / 128, MTOT / 128, 2);        // (8, 64, 2) = 1024 CTAs
    g_gemm<3, false, 1, true, 2, false><<<gqk, 256, SM_P3>>>(
        (const uint16_t*)xh, (const uint16_t*)xl,
        (const uint16_t*)wth, (const uint16_t*)wtl, bq, bk,
        nullptr, qkh, qkl, DIM, DIM, 0, WOFF, QKO);

    //    V projection: fp16 single product, B = Wv natural [in,out] via BT.
    const dim3 gv(DIM / 128, MTOT / 128, 1);         // (8, 64) = 512 CTAs
    g_gemm<1, true, 2, true, 3, true><<<gv, 256, SM_BT>>>(
        (const uint16_t*)x16, nullptr,
        (const uint16_t*)wv16, nullptr, bv, bv,
        (float*)v16, nullptr, nullptr, DIM, DIM, 0, 0, 0);

    // 3) scores = Q @ K^T per batch -> fp32 S  (bf16 3-product)
    const dim3 gs(SEQ / 128, SEQ / 128, BATCH);      // (16, 16, 4) = 1024 CTAs
    g_gemm<3, false, 0, false, 2, false><<<gs, 256, SM_P3>>>(
        (const uint16_t*)qkh, (const uint16_t*)qkl,
        (const uint16_t*)(qkh + QKO), (const uint16_t*)(qkl + QKO),
        nullptr, nullptr,
        s, nullptr, nullptr, SEQ, DIM,
        (size_t)SEQ * DIM, (size_t)SEQ * DIM, (size_t)SEQ * SEQ);

    // 4) softmax -> P fp16
    softmax_f16<<<MTOT / 8, 256>>>(s, p16);

    // 5) out = P @ V per batch (fp16 single product, V natural [s,d] via BT)
    const dim3 go(DIM / 128, SEQ / 128, BATCH);      // (8, 16, 4) = 512 CTAs
    g_gemm<1, true, 0, false, 3, true><<<go, 256, SM_BT>>>(
        (const uint16_t*)p16, nullptr,
        (const uint16_t*)v16, nullptr, nullptr, nullptr,
        out, nullptr, nullptr, DIM, SEQ,
        (size_t)SEQ * SEQ, (size_t)SEQ * DIM, (size_t)SEQ * DIM);
}